// round 6
// baseline (speedup 1.0000x reference)
#include <cuda_runtime.h>
#include <math.h>

#define Bb 16
#define Cc 256
#define Tt 8192
#define KSPLIT 4
#define SL (Bb*Cc*Cc)
#define OUT_ELEMS ((size_t)Bb*Cc*Tt)

typedef unsigned long long u64;

__device__ float g_mean[Bb*Tt];
__device__ float g_varpart[Bb*8];
__device__ float g_covp[(size_t)KSPLIT*SL];
__device__ float g_q[Bb*Cc*32];
__device__ float g_k[Bb*Cc*32];

__device__ __forceinline__ void fma2(u64 &d, u64 a, u64 b){
    asm("fma.rn.f32x2 %0, %1, %2, %0;" : "+l"(d) : "l"(a), "l"(b));
}
__device__ __forceinline__ u64 dup2(float v){
    u64 r; asm("mov.b64 %0, {%1, %1};" : "=l"(r) : "f"(v)); return r;
}
__device__ __forceinline__ float2 unpk(u64 v){
    float2 f; asm("mov.b64 {%0, %1}, %2;" : "=f"(f.x), "=f"(f.y) : "l"(v)); return f;
}

// =============================================================================
// K1: per-(b,t) mean/var over C, float4 per thread. grid (8, Bb)
// =============================================================================
__global__ void __launch_bounds__(256) stats_kernel(const float* __restrict__ x){
    int b = blockIdx.y;
    int t4 = (blockIdx.x*256 + threadIdx.x)*4;
    const float* xp = x + (size_t)b*Cc*Tt + t4;
    float4 s = make_float4(0.f,0.f,0.f,0.f);
    float4 q = make_float4(0.f,0.f,0.f,0.f);
    #pragma unroll 8
    for(int c=0;c<Cc;c++){
        float4 v = *(const float4*)&xp[(size_t)c*Tt];
        s.x+=v.x; s.y+=v.y; s.z+=v.z; s.w+=v.w;
        q.x+=v.x*v.x; q.y+=v.y*v.y; q.z+=v.z*v.z; q.w+=v.w*v.w;
    }
    const float ic = 1.0f/Cc, iv = 1.0f/(Cc-1);
    float4 mean = make_float4(s.x*ic, s.y*ic, s.z*ic, s.w*ic);
    *(float4*)&g_mean[b*Tt + t4] = mean;
    float pv = (q.x - s.x*mean.x)*iv + (q.y - s.y*mean.y)*iv
             + (q.z - s.z*mean.z)*iv + (q.w - s.w*mean.w)*iv;
    __shared__ float red[256];
    int tid = threadIdx.x;
    red[tid]=pv; __syncthreads();
    for(int w=128;w>0;w>>=1){ if(tid<w) red[tid]+=red[tid+w]; __syncthreads(); }
    if(tid==0) g_varpart[b*8+blockIdx.x]=red[0];
}

// =============================================================================
// K2: cov partials; 10 upper 64x64 tiles, 4 K-slices; prefetch next chunk.
// =============================================================================
__constant__ int c_ti[10]={0,0,0,0,1,1,1,2,2,3};
__constant__ int c_tj[10]={0,1,2,3,1,2,3,2,3,3};

__global__ void __launch_bounds__(256) cov_kernel(const float* __restrict__ x){
    int tile=blockIdx.x, b=blockIdx.y, sl=blockIdx.z;
    int i0=c_ti[tile]*64, j0=c_tj[tile]*64;
    bool diag=(i0==j0);
    __shared__ float As[64][32];
    __shared__ float Bs[64][32];
    const float* xb = x + (size_t)b*Cc*Tt;
    const float* mb = g_mean + b*Tt;
    int tid=threadIdx.x;
    int ty=tid>>4, tx=tid&15;
    int lr=tid>>3, lkf=tid&7;
    int sslot = ((lkf ^ ((lr>>2)&7))<<2);
    int swa = ty&7, swb = tx&7;

    u64 acc[4][4];
    #pragma unroll
    for(int i=0;i<4;i++){
        #pragma unroll
        for(int j=0;j<4;j++) acc[i][j]=0ull;
    }

    const int NCH = (Tt/KSPLIT)/32;
    int kbase = sl*(Tt/KSPLIT);
    float4 mv, a0, a1, b0, b1;

#define COV_LOAD(CH) { int kt = kbase + (CH)*32 + lkf*4;                        \
        mv = *(const float4*)&mb[kt];                                           \
        a0 = *(const float4*)&xb[(size_t)(i0+lr   )*Tt + kt];                   \
        a1 = *(const float4*)&xb[(size_t)(i0+lr+32)*Tt + kt];                   \
        if(!diag){                                                              \
            b0 = *(const float4*)&xb[(size_t)(j0+lr   )*Tt + kt];               \
            b1 = *(const float4*)&xb[(size_t)(j0+lr+32)*Tt + kt];               \
        } }

    COV_LOAD(0);
    #pragma unroll 1
    for(int ch=0; ch<NCH; ++ch){
        __syncthreads();
        *(float4*)&As[lr   ][sslot] = make_float4(a0.x-mv.x,a0.y-mv.y,a0.z-mv.z,a0.w-mv.w);
        *(float4*)&As[lr+32][sslot] = make_float4(a1.x-mv.x,a1.y-mv.y,a1.z-mv.z,a1.w-mv.w);
        if(!diag){
            *(float4*)&Bs[lr   ][sslot] = make_float4(b0.x-mv.x,b0.y-mv.y,b0.z-mv.z,b0.w-mv.w);
            *(float4*)&Bs[lr+32][sslot] = make_float4(b1.x-mv.x,b1.y-mv.y,b1.z-mv.z,b1.w-mv.w);
        }
        __syncthreads();
        if(ch+1<NCH) COV_LOAD(ch+1);   // prefetch flies during compute
        float (*Bp)[32] = diag ? As : Bs;
        #pragma unroll
        for(int k4=0;k4<8;k4++){
            int sa = ((k4^swa)<<2);
            int sb = ((k4^swb)<<2);
            longlong2 av[4], bv[4];
            #pragma unroll
            for(int i=0;i<4;i++) av[i] = *(const longlong2*)&As[ty*4+i][sa];
            #pragma unroll
            for(int j=0;j<4;j++) bv[j] = *(const longlong2*)&Bp[tx*4+j][sb];
            #pragma unroll
            for(int i=0;i<4;i++){
                #pragma unroll
                for(int j=0;j<4;j++){
                    fma2(acc[i][j], (u64)av[i].x, (u64)bv[j].x);
                    fma2(acc[i][j], (u64)av[i].y, (u64)bv[j].y);
                }
            }
        }
    }
#undef COV_LOAD

    float* cp = g_covp + (size_t)(sl*Bb+b)*Cc*Cc;
    #pragma unroll
    for(int i=0;i<4;i++){
        float r[4];
        #pragma unroll
        for(int j=0;j<4;j++){ float2 f=unpk(acc[i][j]); r[j]=f.x+f.y; }
        int ci = i0+ty*4+i;
        *(float4*)&cp[(size_t)ci*Cc + j0 + tx*4] = make_float4(r[0],r[1],r[2],r[3]);
        if(!diag){
            #pragma unroll
            for(int j=0;j<4;j++) cp[(size_t)(j0+tx*4+j)*Cc + ci] = r[j];
        }
    }
}

// =============================================================================
// K3: reduce 4 cov slices -> pcc row, then q/k projections. block per (c,b)
// =============================================================================
__global__ void __launch_bounds__(256) pccqk_kernel(const float* __restrict__ qw, const float* __restrict__ qb,
                                                    const float* __restrict__ kw, const float* __restrict__ kb){
    int c=blockIdx.x, b=blockIdx.y, tid=threadIdx.x;
    __shared__ float row[256];
    __shared__ float sp[64][4];
    __shared__ float sden;
    if(tid==0){
        float d=0.f;
        #pragma unroll
        for(int i=0;i<8;i++) d += g_varpart[b*8+i];
        sden = 1.0f/d;
    }
    size_t base = ((size_t)b*Cc + c)*Cc + tid;
    float v = g_covp[base] + g_covp[(size_t)SL + base]
            + g_covp[2*(size_t)SL + base] + g_covp[3*(size_t)SL + base];
    __syncthreads();
    row[tid] = v * sden;
    __syncthreads();
    int e = tid>>2, seg = tid&3;
    const float* w = (e<32) ? (qw + e*Cc) : (kw + (e-32)*Cc);
    float p=0.f;
    int d0 = seg*64;
    #pragma unroll 8
    for(int d=0; d<64; d++) p += row[d0+d]*__ldg(&w[d0+d]);
    sp[e][seg]=p;
    __syncthreads();
    if(tid<64){
        float r = sp[tid][0]+sp[tid][1]+sp[tid][2]+sp[tid][3];
        if(tid<32) g_q[((size_t)b*Cc+c)*32 + tid]      = r + qb[tid];
        else       g_k[((size_t)b*Cc+c)*32 + (tid-32)] = r + kb[tid-32];
    }
}

// =============================================================================
// K4: scores + softmax, warp-per-query. Block = (32 queries, b); grid (8, Bb).
// K tile loaded once per 32 queries. Writes attn in natural [c][d] layout.
// =============================================================================
__global__ void __launch_bounds__(256) attn_kernel(float* __restrict__ out){
    int bg = blockIdx.x, b = blockIdx.y;
    int tid = threadIdx.x, w = tid>>5, lane = tid&31;
    __shared__ float ks[256][36];
    __shared__ float qs[32][36];
    const float* kp = g_k + (size_t)b*Cc*32;
    int c0 = bg*32;
    #pragma unroll
    for(int p=0;p<8;p++){
        int idx = tid + p*256;
        int d = idx>>3, e4 = (idx&7)*4;
        *(float4*)&ks[d][e4] = *(const float4*)&kp[d*32 + e4];
    }
    {
        int q = tid>>3, e4 = (tid&7)*4;
        *(float4*)&qs[q][e4] = *(const float4*)&g_q[((size_t)b*Cc + c0 + q)*32 + e4];
    }
    __syncthreads();
    float* ao = out + OUT_ELEMS + ((size_t)b*Cc + c0)*Cc;
    #pragma unroll
    for(int qi=0; qi<4; qi++){
        int q = w*4 + qi;
        float s[8];
        #pragma unroll
        for(int m=0;m<8;m++) s[m]=0.f;
        #pragma unroll
        for(int e4=0;e4<8;e4++){
            float4 qv = *(const float4*)&qs[q][e4*4];
            #pragma unroll
            for(int m=0;m<8;m++){
                float4 kv = *(const float4*)&ks[m*32+lane][e4*4];
                s[m] += qv.x*kv.x + qv.y*kv.y + qv.z*kv.z + qv.w*kv.w;
            }
        }
        float mx = s[0]*(1.0f/16.0f);
        #pragma unroll
        for(int m=0;m<8;m++){ s[m] *= (1.0f/16.0f); mx = fmaxf(mx, s[m]); }
        #pragma unroll
        for(int d=16; d>0; d>>=1) mx = fmaxf(mx, __shfl_xor_sync(0xffffffffu, mx, d));
        float ev[8], sm=0.f;
        #pragma unroll
        for(int m=0;m<8;m++){ ev[m] = expf(s[m]-mx); sm += ev[m]; }
        #pragma unroll
        for(int d=16; d>0; d>>=1) sm += __shfl_xor_sync(0xffffffffu, sm, d);
        float inv = 1.0f/sm;
        #pragma unroll
        for(int m=0;m<8;m++) ao[(size_t)q*Cc + m*32 + lane] = ev[m]*inv;
    }
}

// =============================================================================
// K5: out = attn @ x. Tile 64(c) x 128(t), K=256 in 8 chunks of 32.
// attn read natively [c][d] from d_out; x natively [d][t]; A pre-duplicated
// as f32x2 pairs in smem; double buffer, 1 sync/chunk. 67.5KB dynamic smem.
// =============================================================================
__global__ void __launch_bounds__(256,2) out_gemm(const float* __restrict__ x,
                                                  const float* __restrict__ attn,
                                                  float* __restrict__ out){
    extern __shared__ char dsm[];
    u64   (*As2)[64][33]  = (u64  (*)[64][33])dsm;                  // 2 x 16.9KB
    float (*Bs )[32][132] = (float(*)[32][132])(dsm + 2*64*33*8);   // 2 x 16.9KB

    int tb=blockIdx.x, cb=blockIdx.y, b=blockIdx.z;
    int t0 = tb*128, c0 = cb*64;
    const float* at = attn + (size_t)b*Cc*Cc;
    const float* xb = x + (size_t)b*Cc*Tt;
    int tid=threadIdx.x, ty=tid>>4, tx=tid&15;
    int lr=tid>>3, lf=tid&7;

    u64 acc[4][4];
    #pragma unroll
    for(int i=0;i<4;i++){
        #pragma unroll
        for(int j=0;j<4;j++) acc[i][j]=0ull;
    }

    float4 aA, aB, bv0, bv1, bv2, bv3;
#define OG_LOAD(D0) {                                                          \
        aA  = *(const float4*)&at[(size_t)(c0+lr   )*Cc + (D0) + lf*4];         \
        aB  = *(const float4*)&at[(size_t)(c0+lr+32)*Cc + (D0) + lf*4];         \
        const float* xr = &xb[(size_t)((D0)+lr)*Tt + t0 + lf*4];                \
        bv0 = *(const float4*)&xr[0];   bv1 = *(const float4*)&xr[32];          \
        bv2 = *(const float4*)&xr[64];  bv3 = *(const float4*)&xr[96]; }
#define OG_STORE(BUF) {                                                        \
        As2[BUF][lr   ][lf*4+0]=dup2(aA.x); As2[BUF][lr   ][lf*4+1]=dup2(aA.y); \
        As2[BUF][lr   ][lf*4+2]=dup2(aA.z); As2[BUF][lr   ][lf*4+3]=dup2(aA.w); \
        As2[BUF][lr+32][lf*4+0]=dup2(aB.x); As2[BUF][lr+32][lf*4+1]=dup2(aB.y); \
        As2[BUF][lr+32][lf*4+2]=dup2(aB.z); As2[BUF][lr+32][lf*4+3]=dup2(aB.w); \
        *(float4*)&Bs[BUF][lr][lf*4+ 0]=bv0; *(float4*)&Bs[BUF][lr][lf*4+32]=bv1;\
        *(float4*)&Bs[BUF][lr][lf*4+64]=bv2; *(float4*)&Bs[BUF][lr][lf*4+96]=bv3; }

    OG_LOAD(0);
    OG_STORE(0);
    __syncthreads();
    #pragma unroll 1
    for(int ch=0; ch<8; ++ch){
        int buf = ch&1;
        if(ch<7) OG_LOAD((ch+1)*32);
        #pragma unroll 8
        for(int kk=0;kk<32;kk++){
            u64 a0 = As2[buf][ty*4+0][kk];
            u64 a1 = As2[buf][ty*4+1][kk];
            u64 a2 = As2[buf][ty*4+2][kk];
            u64 a3 = As2[buf][ty*4+3][kk];
            longlong2 B0 = *(const longlong2*)&Bs[buf][kk][tx*4];
            longlong2 B1 = *(const longlong2*)&Bs[buf][kk][tx*4+64];
            fma2(acc[0][0],a0,(u64)B0.x); fma2(acc[0][1],a0,(u64)B0.y);
            fma2(acc[0][2],a0,(u64)B1.x); fma2(acc[0][3],a0,(u64)B1.y);
            fma2(acc[1][0],a1,(u64)B0.x); fma2(acc[1][1],a1,(u64)B0.y);
            fma2(acc[1][2],a1,(u64)B1.x); fma2(acc[1][3],a1,(u64)B1.y);
            fma2(acc[2][0],a2,(u64)B0.x); fma2(acc[2][1],a2,(u64)B0.y);
            fma2(acc[2][2],a2,(u64)B1.x); fma2(acc[2][3],a2,(u64)B1.y);
            fma2(acc[3][0],a3,(u64)B0.x); fma2(acc[3][1],a3,(u64)B0.y);
            fma2(acc[3][2],a3,(u64)B1.x); fma2(acc[3][3],a3,(u64)B1.y);
        }
        if(ch<7){ OG_STORE(buf^1); __syncthreads(); }
    }
#undef OG_LOAD
#undef OG_STORE

    float* ob = out + (size_t)b*Cc*Tt;
    #pragma unroll
    for(int i=0;i<4;i++){
        int r = c0 + ty*4 + i;
        float2 f0=unpk(acc[i][0]), f1=unpk(acc[i][1]);
        *(float4*)&ob[(size_t)r*Tt + t0 + tx*4]      = make_float4(f0.x,f0.y,f1.x,f1.y);
        float2 f2=unpk(acc[i][2]), f3=unpk(acc[i][3]);
        *(float4*)&ob[(size_t)r*Tt + t0 + tx*4 + 64] = make_float4(f2.x,f2.y,f3.x,f3.y);
    }
}

// =============================================================================
extern "C" void kernel_launch(void* const* d_in, const int* in_sizes, int n_in,
                              void* d_out, int out_size){
    const float* x  = (const float*)d_in[0];
    const float* qw = (const float*)d_in[1];
    const float* qb = (const float*)d_in[2];
    const float* kw = (const float*)d_in[3];
    const float* kb = (const float*)d_in[4];
    float* out = (float*)d_out;

    const int og_smem = 2*64*33*8 + 2*32*132*4;   // 67584 bytes
    cudaFuncSetAttribute(out_gemm, cudaFuncAttributeMaxDynamicSharedMemorySize, og_smem);

    stats_kernel<<<dim3(Tt/1024, Bb), 256>>>(x);
    cov_kernel  <<<dim3(10, Bb, KSPLIT), 256>>>(x);
    pccqk_kernel<<<dim3(Cc, Bb), 256>>>(qw, qb, kw, kb);
    attn_kernel <<<dim3(Cc/32, Bb), 256>>>(out);
    out_gemm    <<<dim3(Tt/128, Cc/64, Bb), 256, og_smem>>>(x, out + OUT_ELEMS, out);
}

// round 7
// speedup vs baseline: 1.0019x; 1.0019x over previous
#include <cuda_runtime.h>
#include <math.h>

#define Bb 16
#define Cc 256
#define Tt 8192
#define KSPLIT 4
#define SL (Bb*Cc*Cc)
#define OUT_ELEMS ((size_t)Bb*Cc*Tt)

typedef unsigned long long u64;

__device__ float g_mean[Bb*Tt];
__device__ float g_varpart[Bb*8];
__device__ float g_covp[(size_t)KSPLIT*SL];
__device__ float g_q[Bb*Cc*32];
__device__ float g_k[Bb*Cc*32];

__device__ __forceinline__ void fma2(u64 &d, u64 a, u64 b){
    asm("fma.rn.f32x2 %0, %1, %2, %0;" : "+l"(d) : "l"(a), "l"(b));
}
__device__ __forceinline__ u64 dup2(float v){
    u64 r; asm("mov.b64 %0, {%1, %1};" : "=l"(r) : "f"(v)); return r;
}
__device__ __forceinline__ float2 unpk(u64 v){
    float2 f; asm("mov.b64 {%0, %1}, %2;" : "=f"(f.x), "=f"(f.y) : "l"(v)); return f;
}

// =============================================================================
// K1: per-(b,t) mean/var over C, float4 per thread. grid (8, Bb)
// =============================================================================
__global__ void __launch_bounds__(256) stats_kernel(const float* __restrict__ x){
    int b = blockIdx.y;
    int t4 = (blockIdx.x*256 + threadIdx.x)*4;
    const float* xp = x + (size_t)b*Cc*Tt + t4;
    float4 s = make_float4(0.f,0.f,0.f,0.f);
    float4 q = make_float4(0.f,0.f,0.f,0.f);
    #pragma unroll 8
    for(int c=0;c<Cc;c++){
        float4 v = *(const float4*)&xp[(size_t)c*Tt];
        s.x+=v.x; s.y+=v.y; s.z+=v.z; s.w+=v.w;
        q.x+=v.x*v.x; q.y+=v.y*v.y; q.z+=v.z*v.z; q.w+=v.w*v.w;
    }
    const float ic = 1.0f/Cc, iv = 1.0f/(Cc-1);
    float4 mean = make_float4(s.x*ic, s.y*ic, s.z*ic, s.w*ic);
    *(float4*)&g_mean[b*Tt + t4] = mean;
    float pv = (q.x - s.x*mean.x)*iv + (q.y - s.y*mean.y)*iv
             + (q.z - s.z*mean.z)*iv + (q.w - s.w*mean.w)*iv;
    __shared__ float red[256];
    int tid = threadIdx.x;
    red[tid]=pv; __syncthreads();
    for(int w=128;w>0;w>>=1){ if(tid<w) red[tid]+=red[tid+w]; __syncthreads(); }
    if(tid==0) g_varpart[b*8+blockIdx.x]=red[0];
}

// =============================================================================
// K2: cov partials; 10 upper 64x64 tiles, 4 K-slices; prefetch next chunk.
// =============================================================================
__constant__ int c_ti[10]={0,0,0,0,1,1,1,2,2,3};
__constant__ int c_tj[10]={0,1,2,3,1,2,3,2,3,3};

__global__ void __launch_bounds__(256) cov_kernel(const float* __restrict__ x){
    int tile=blockIdx.x, b=blockIdx.y, sl=blockIdx.z;
    int i0=c_ti[tile]*64, j0=c_tj[tile]*64;
    bool diag=(i0==j0);
    __shared__ float As[64][32];
    __shared__ float Bs[64][32];
    const float* xb = x + (size_t)b*Cc*Tt;
    const float* mb = g_mean + b*Tt;
    int tid=threadIdx.x;
    int ty=tid>>4, tx=tid&15;
    int lr=tid>>3, lkf=tid&7;
    int sslot = ((lkf ^ ((lr>>2)&7))<<2);
    int swa = ty&7, swb = tx&7;

    u64 acc[4][4];
    #pragma unroll
    for(int i=0;i<4;i++){
        #pragma unroll
        for(int j=0;j<4;j++) acc[i][j]=0ull;
    }

    const int NCH = (Tt/KSPLIT)/32;
    int kbase = sl*(Tt/KSPLIT);
    float4 mv, a0, a1, b0, b1;

#define COV_LOAD(CH) { int kt = kbase + (CH)*32 + lkf*4;                        \
        mv = *(const float4*)&mb[kt];                                           \
        a0 = *(const float4*)&xb[(size_t)(i0+lr   )*Tt + kt];                   \
        a1 = *(const float4*)&xb[(size_t)(i0+lr+32)*Tt + kt];                   \
        if(!diag){                                                              \
            b0 = *(const float4*)&xb[(size_t)(j0+lr   )*Tt + kt];               \
            b1 = *(const float4*)&xb[(size_t)(j0+lr+32)*Tt + kt];               \
        } }

    COV_LOAD(0);
    #pragma unroll 1
    for(int ch=0; ch<NCH; ++ch){
        __syncthreads();
        *(float4*)&As[lr   ][sslot] = make_float4(a0.x-mv.x,a0.y-mv.y,a0.z-mv.z,a0.w-mv.w);
        *(float4*)&As[lr+32][sslot] = make_float4(a1.x-mv.x,a1.y-mv.y,a1.z-mv.z,a1.w-mv.w);
        if(!diag){
            *(float4*)&Bs[lr   ][sslot] = make_float4(b0.x-mv.x,b0.y-mv.y,b0.z-mv.z,b0.w-mv.w);
            *(float4*)&Bs[lr+32][sslot] = make_float4(b1.x-mv.x,b1.y-mv.y,b1.z-mv.z,b1.w-mv.w);
        }
        __syncthreads();
        if(ch+1<NCH) COV_LOAD(ch+1);   // prefetch flies during compute
        float (*Bp)[32] = diag ? As : Bs;
        #pragma unroll
        for(int k4=0;k4<8;k4++){
            int sa = ((k4^swa)<<2);
            int sb = ((k4^swb)<<2);
            longlong2 av[4], bv[4];
            #pragma unroll
            for(int i=0;i<4;i++) av[i] = *(const longlong2*)&As[ty*4+i][sa];
            #pragma unroll
            for(int j=0;j<4;j++) bv[j] = *(const longlong2*)&Bp[tx*4+j][sb];
            #pragma unroll
            for(int i=0;i<4;i++){
                #pragma unroll
                for(int j=0;j<4;j++){
                    fma2(acc[i][j], (u64)av[i].x, (u64)bv[j].x);
                    fma2(acc[i][j], (u64)av[i].y, (u64)bv[j].y);
                }
            }
        }
    }
#undef COV_LOAD

    float* cp = g_covp + (size_t)(sl*Bb+b)*Cc*Cc;
    #pragma unroll
    for(int i=0;i<4;i++){
        float r[4];
        #pragma unroll
        for(int j=0;j<4;j++){ float2 f=unpk(acc[i][j]); r[j]=f.x+f.y; }
        int ci = i0+ty*4+i;
        *(float4*)&cp[(size_t)ci*Cc + j0 + tx*4] = make_float4(r[0],r[1],r[2],r[3]);
        if(!diag){
            #pragma unroll
            for(int j=0;j<4;j++) cp[(size_t)(j0+tx*4+j)*Cc + ci] = r[j];
        }
    }
}

// =============================================================================
// K3: reduce 4 cov slices -> pcc row, then q/k projections. block per (c,b)
// =============================================================================
__global__ void __launch_bounds__(256) pccqk_kernel(const float* __restrict__ qw, const float* __restrict__ qb,
                                                    const float* __restrict__ kw, const float* __restrict__ kb){
    int c=blockIdx.x, b=blockIdx.y, tid=threadIdx.x;
    __shared__ float row[256];
    __shared__ float sp[64][4];
    __shared__ float sden;
    if(tid==0){
        float d=0.f;
        #pragma unroll
        for(int i=0;i<8;i++) d += g_varpart[b*8+i];
        sden = 1.0f/d;
    }
    size_t base = ((size_t)b*Cc + c)*Cc + tid;
    float v = g_covp[base] + g_covp[(size_t)SL + base]
            + g_covp[2*(size_t)SL + base] + g_covp[3*(size_t)SL + base];
    __syncthreads();
    row[tid] = v * sden;
    __syncthreads();
    int e = tid>>2, seg = tid&3;
    const float* w = (e<32) ? (qw + e*Cc) : (kw + (e-32)*Cc);
    float p=0.f;
    int d0 = seg*64;
    #pragma unroll 8
    for(int d=0; d<64; d++) p += row[d0+d]*__ldg(&w[d0+d]);
    sp[e][seg]=p;
    __syncthreads();
    if(tid<64){
        float r = sp[tid][0]+sp[tid][1]+sp[tid][2]+sp[tid][3];
        if(tid<32) g_q[((size_t)b*Cc+c)*32 + tid]      = r + qb[tid];
        else       g_k[((size_t)b*Cc+c)*32 + (tid-32)] = r + kb[tid-32];
    }
}

// =============================================================================
// K4: scores + softmax, warp-per-query. Block = (32 queries, b); grid (8, Bb).
// K tile loaded once per 32 queries. Writes attn in natural [c][d] layout.
// =============================================================================
__global__ void __launch_bounds__(256) attn_kernel(float* __restrict__ out){
    int bg = blockIdx.x, b = blockIdx.y;
    int tid = threadIdx.x, w = tid>>5, lane = tid&31;
    __shared__ float ks[256][36];
    __shared__ float qs[32][36];
    const float* kp = g_k + (size_t)b*Cc*32;
    int c0 = bg*32;
    #pragma unroll
    for(int p=0;p<8;p++){
        int idx = tid + p*256;
        int d = idx>>3, e4 = (idx&7)*4;
        *(float4*)&ks[d][e4] = *(const float4*)&kp[d*32 + e4];
    }
    {
        int q = tid>>3, e4 = (tid&7)*4;
        *(float4*)&qs[q][e4] = *(const float4*)&g_q[((size_t)b*Cc + c0 + q)*32 + e4];
    }
    __syncthreads();
    float* ao = out + OUT_ELEMS + ((size_t)b*Cc + c0)*Cc;
    #pragma unroll
    for(int qi=0; qi<4; qi++){
        int q = w*4 + qi;
        float s[8];
        #pragma unroll
        for(int m=0;m<8;m++) s[m]=0.f;
        #pragma unroll
        for(int e4=0;e4<8;e4++){
            float4 qv = *(const float4*)&qs[q][e4*4];
            #pragma unroll
            for(int m=0;m<8;m++){
                float4 kv = *(const float4*)&ks[m*32+lane][e4*4];
                s[m] += qv.x*kv.x + qv.y*kv.y + qv.z*kv.z + qv.w*kv.w;
            }
        }
        float mx = s[0]*(1.0f/16.0f);
        #pragma unroll
        for(int m=0;m<8;m++){ s[m] *= (1.0f/16.0f); mx = fmaxf(mx, s[m]); }
        #pragma unroll
        for(int d=16; d>0; d>>=1) mx = fmaxf(mx, __shfl_xor_sync(0xffffffffu, mx, d));
        float ev[8], sm=0.f;
        #pragma unroll
        for(int m=0;m<8;m++){ ev[m] = expf(s[m]-mx); sm += ev[m]; }
        #pragma unroll
        for(int d=16; d>0; d>>=1) sm += __shfl_xor_sync(0xffffffffu, sm, d);
        float inv = 1.0f/sm;
        #pragma unroll
        for(int m=0;m<8;m++) ao[(size_t)q*Cc + m*32 + lane] = ev[m]*inv;
    }
}

// =============================================================================
// K5: out = attn @ x. Tile 64(c) x 128(t), K=256 in 8 chunks of 32.
// attn read natively [c][d] from d_out; x natively [d][t]; A pre-duplicated
// as f32x2 pairs in smem; double buffer, 1 sync/chunk. 67.5KB dynamic smem.
// =============================================================================
__global__ void __launch_bounds__(256,2) out_gemm(const float* __restrict__ x,
                                                  const float* __restrict__ attn,
                                                  float* __restrict__ out){
    extern __shared__ char dsm[];
    u64   (*As2)[64][33]  = (u64  (*)[64][33])dsm;                  // 2 x 16.9KB
    float (*Bs )[32][132] = (float(*)[32][132])(dsm + 2*64*33*8);   // 2 x 16.9KB

    int tb=blockIdx.x, cb=blockIdx.y, b=blockIdx.z;
    int t0 = tb*128, c0 = cb*64;
    const float* at = attn + (size_t)b*Cc*Cc;
    const float* xb = x + (size_t)b*Cc*Tt;
    int tid=threadIdx.x, ty=tid>>4, tx=tid&15;
    int lr=tid>>3, lf=tid&7;

    u64 acc[4][4];
    #pragma unroll
    for(int i=0;i<4;i++){
        #pragma unroll
        for(int j=0;j<4;j++) acc[i][j]=0ull;
    }

    float4 aA, aB, bv0, bv1, bv2, bv3;
#define OG_LOAD(D0) {                                                          \
        aA  = *(const float4*)&at[(size_t)(c0+lr   )*Cc + (D0) + lf*4];         \
        aB  = *(const float4*)&at[(size_t)(c0+lr+32)*Cc + (D0) + lf*4];         \
        const float* xr = &xb[(size_t)((D0)+lr)*Tt + t0 + lf*4];                \
        bv0 = *(const float4*)&xr[0];   bv1 = *(const float4*)&xr[32];          \
        bv2 = *(const float4*)&xr[64];  bv3 = *(const float4*)&xr[96]; }
#define OG_STORE(BUF) {                                                        \
        As2[BUF][lr   ][lf*4+0]=dup2(aA.x); As2[BUF][lr   ][lf*4+1]=dup2(aA.y); \
        As2[BUF][lr   ][lf*4+2]=dup2(aA.z); As2[BUF][lr   ][lf*4+3]=dup2(aA.w); \
        As2[BUF][lr+32][lf*4+0]=dup2(aB.x); As2[BUF][lr+32][lf*4+1]=dup2(aB.y); \
        As2[BUF][lr+32][lf*4+2]=dup2(aB.z); As2[BUF][lr+32][lf*4+3]=dup2(aB.w); \
        *(float4*)&Bs[BUF][lr][lf*4+ 0]=bv0; *(float4*)&Bs[BUF][lr][lf*4+32]=bv1;\
        *(float4*)&Bs[BUF][lr][lf*4+64]=bv2; *(float4*)&Bs[BUF][lr][lf*4+96]=bv3; }

    OG_LOAD(0);
    OG_STORE(0);
    __syncthreads();
    #pragma unroll 1
    for(int ch=0; ch<8; ++ch){
        int buf = ch&1;
        if(ch<7) OG_LOAD((ch+1)*32);
        #pragma unroll 8
        for(int kk=0;kk<32;kk++){
            u64 a0 = As2[buf][ty*4+0][kk];
            u64 a1 = As2[buf][ty*4+1][kk];
            u64 a2 = As2[buf][ty*4+2][kk];
            u64 a3 = As2[buf][ty*4+3][kk];
            longlong2 B0 = *(const longlong2*)&Bs[buf][kk][tx*4];
            longlong2 B1 = *(const longlong2*)&Bs[buf][kk][tx*4+64];
            fma2(acc[0][0],a0,(u64)B0.x); fma2(acc[0][1],a0,(u64)B0.y);
            fma2(acc[0][2],a0,(u64)B1.x); fma2(acc[0][3],a0,(u64)B1.y);
            fma2(acc[1][0],a1,(u64)B0.x); fma2(acc[1][1],a1,(u64)B0.y);
            fma2(acc[1][2],a1,(u64)B1.x); fma2(acc[1][3],a1,(u64)B1.y);
            fma2(acc[2][0],a2,(u64)B0.x); fma2(acc[2][1],a2,(u64)B0.y);
            fma2(acc[2][2],a2,(u64)B1.x); fma2(acc[2][3],a2,(u64)B1.y);
            fma2(acc[3][0],a3,(u64)B0.x); fma2(acc[3][1],a3,(u64)B0.y);
            fma2(acc[3][2],a3,(u64)B1.x); fma2(acc[3][3],a3,(u64)B1.y);
        }
        if(ch<7){ OG_STORE(buf^1); __syncthreads(); }
    }
#undef OG_LOAD
#undef OG_STORE

    float* ob = out + (size_t)b*Cc*Tt;
    #pragma unroll
    for(int i=0;i<4;i++){
        int r = c0 + ty*4 + i;
        float2 f0=unpk(acc[i][0]), f1=unpk(acc[i][1]);
        *(float4*)&ob[(size_t)r*Tt + t0 + tx*4]      = make_float4(f0.x,f0.y,f1.x,f1.y);
        float2 f2=unpk(acc[i][2]), f3=unpk(acc[i][3]);
        *(float4*)&ob[(size_t)r*Tt + t0 + tx*4 + 64] = make_float4(f2.x,f2.y,f3.x,f3.y);
    }
}

// =============================================================================
extern "C" void kernel_launch(void* const* d_in, const int* in_sizes, int n_in,
                              void* d_out, int out_size){
    const float* x  = (const float*)d_in[0];
    const float* qw = (const float*)d_in[1];
    const float* qb = (const float*)d_in[2];
    const float* kw = (const float*)d_in[3];
    const float* kb = (const float*)d_in[4];
    float* out = (float*)d_out;

    const int og_smem = 2*64*33*8 + 2*32*132*4;   // 67584 bytes
    cudaFuncSetAttribute(out_gemm, cudaFuncAttributeMaxDynamicSharedMemorySize, og_smem);

    stats_kernel<<<dim3(Tt/1024, Bb), 256>>>(x);
    cov_kernel  <<<dim3(10, Bb, KSPLIT), 256>>>(x);
    pccqk_kernel<<<dim3(Cc, Bb), 256>>>(qw, qb, kw, kb);
    attn_kernel <<<dim3(Cc/32, Bb), 256>>>(out);
    out_gemm    <<<dim3(Tt/128, Cc/64, Bb), 256, og_smem>>>(x, out + OUT_ELEMS, out);
}

// round 8
// speedup vs baseline: 1.0691x; 1.0671x over previous
#include <cuda_runtime.h>
#include <math.h>

#define Bb 16
#define Cc 256
#define Tt 8192
#define KSPLIT 4
#define SL (Bb*Cc*Cc)
#define OUT_ELEMS ((size_t)Bb*Cc*Tt)

typedef unsigned long long u64;

// ---------------- scratch (static device globals; no allocation) -------------
__device__ float g_mean[Bb*Tt];
__device__ float g_varpart[Bb*8];
__device__ float g_covp[(size_t)KSPLIT*SL];
__device__ float g_attnT[(size_t)Bb*Cc*Cc];   // attn transposed [b][d][c]
__device__ float g_q[Bb*Cc*32];
__device__ float g_k[Bb*Cc*32];

// ---------------- f32x2 packed-FMA helpers (Blackwell) -----------------------
__device__ __forceinline__ void fma2(u64 &d, u64 a, u64 b){
    asm("fma.rn.f32x2 %0, %1, %2, %0;" : "+l"(d) : "l"(a), "l"(b));
}
__device__ __forceinline__ u64 dup2(float v){
    u64 r; asm("mov.b64 %0, {%1, %1};" : "=l"(r) : "f"(v)); return r;
}
__device__ __forceinline__ float2 unpk(u64 v){
    float2 f; asm("mov.b64 {%0, %1}, %2;" : "=f"(f.x), "=f"(f.y) : "l"(v)); return f;
}

// =============================================================================
// K1: per-(b,t) mean/var over C, float4 per thread. grid (8, Bb)
// =============================================================================
__global__ void __launch_bounds__(256) stats_kernel(const float* __restrict__ x){
    int b = blockIdx.y;
    int t4 = (blockIdx.x*256 + threadIdx.x)*4;
    const float* xp = x + (size_t)b*Cc*Tt + t4;
    float4 s = make_float4(0.f,0.f,0.f,0.f);
    float4 q = make_float4(0.f,0.f,0.f,0.f);
    #pragma unroll 8
    for(int c=0;c<Cc;c++){
        float4 v = *(const float4*)&xp[(size_t)c*Tt];
        s.x+=v.x; s.y+=v.y; s.z+=v.z; s.w+=v.w;
        q.x+=v.x*v.x; q.y+=v.y*v.y; q.z+=v.z*v.z; q.w+=v.w*v.w;
    }
    const float ic = 1.0f/Cc, iv = 1.0f/(Cc-1);
    float4 mean = make_float4(s.x*ic, s.y*ic, s.z*ic, s.w*ic);
    *(float4*)&g_mean[b*Tt + t4] = mean;
    float pv = (q.x - s.x*mean.x)*iv + (q.y - s.y*mean.y)*iv
             + (q.z - s.z*mean.z)*iv + (q.w - s.w*mean.w)*iv;
    __shared__ float red[256];
    int tid = threadIdx.x;
    red[tid]=pv; __syncthreads();
    for(int w=128;w>0;w>>=1){ if(tid<w) red[tid]+=red[tid+w]; __syncthreads(); }
    if(tid==0) g_varpart[b*8+blockIdx.x]=red[0];
}

// =============================================================================
// K2: cov partials (EXACT R2 version — known-good). 10 upper 64x64 tiles,
// 4 K-slices, K-packed f32x2, XOR-swizzled smem.
// =============================================================================
__constant__ int c_ti[10]={0,0,0,0,1,1,1,2,2,3};
__constant__ int c_tj[10]={0,1,2,3,1,2,3,2,3,3};

__global__ void __launch_bounds__(256) cov_kernel(const float* __restrict__ x){
    int tile=blockIdx.x, b=blockIdx.y, sl=blockIdx.z;
    int i0=c_ti[tile]*64, j0=c_tj[tile]*64;
    bool diag=(i0==j0);
    __shared__ float As[64][32];
    __shared__ float Bs[64][32];
    const float* xb = x + (size_t)b*Cc*Tt;
    const float* mb = g_mean + b*Tt;
    int tid=threadIdx.x;
    int ty=tid>>4, tx=tid&15;
    int lr=tid>>3, lkf=tid&7;
    int sslot = ((lkf ^ ((lr>>2)&7))<<2);
    int swa = ty&7, swb = tx&7;

    u64 acc[4][4];
    #pragma unroll
    for(int i=0;i<4;i++){
        #pragma unroll
        for(int j=0;j<4;j++) acc[i][j]=0ull;
    }

    int kbase = sl*(Tt/KSPLIT);
    for(int ch=0; ch<(Tt/KSPLIT)/32; ++ch){
        int kt = kbase + ch*32 + lkf*4;
        float4 mv = *(const float4*)&mb[kt];
        float4 a0 = *(const float4*)&xb[(size_t)(i0+lr   )*Tt + kt];
        float4 a1 = *(const float4*)&xb[(size_t)(i0+lr+32)*Tt + kt];
        float4 b0, b1;
        if(!diag){
            b0 = *(const float4*)&xb[(size_t)(j0+lr   )*Tt + kt];
            b1 = *(const float4*)&xb[(size_t)(j0+lr+32)*Tt + kt];
        }
        __syncthreads();
        *(float4*)&As[lr   ][sslot] = make_float4(a0.x-mv.x,a0.y-mv.y,a0.z-mv.z,a0.w-mv.w);
        *(float4*)&As[lr+32][sslot] = make_float4(a1.x-mv.x,a1.y-mv.y,a1.z-mv.z,a1.w-mv.w);
        if(!diag){
            *(float4*)&Bs[lr   ][sslot] = make_float4(b0.x-mv.x,b0.y-mv.y,b0.z-mv.z,b0.w-mv.w);
            *(float4*)&Bs[lr+32][sslot] = make_float4(b1.x-mv.x,b1.y-mv.y,b1.z-mv.z,b1.w-mv.w);
        }
        __syncthreads();
        float (*Bp)[32] = diag ? As : Bs;
        #pragma unroll
        for(int k4=0;k4<8;k4++){
            int sa = ((k4^swa)<<2);
            int sb = ((k4^swb)<<2);
            longlong2 av[4], bv[4];
            #pragma unroll
            for(int i=0;i<4;i++) av[i] = *(const longlong2*)&As[ty*4+i][sa];
            #pragma unroll
            for(int j=0;j<4;j++) bv[j] = *(const longlong2*)&Bp[tx*4+j][sb];
            #pragma unroll
            for(int i=0;i<4;i++){
                #pragma unroll
                for(int j=0;j<4;j++){
                    fma2(acc[i][j], (u64)av[i].x, (u64)bv[j].x);
                    fma2(acc[i][j], (u64)av[i].y, (u64)bv[j].y);
                }
            }
        }
    }

    float* cp = g_covp + (size_t)(sl*Bb+b)*Cc*Cc;
    #pragma unroll
    for(int i=0;i<4;i++){
        float r[4];
        #pragma unroll
        for(int j=0;j<4;j++){ float2 f=unpk(acc[i][j]); r[j]=f.x+f.y; }
        int ci = i0+ty*4+i;
        *(float4*)&cp[(size_t)ci*Cc + j0 + tx*4] = make_float4(r[0],r[1],r[2],r[3]);
        if(!diag){
            #pragma unroll
            for(int j=0;j<4;j++) cp[(size_t)(j0+tx*4+j)*Cc + ci] = r[j];
        }
    }
}

// =============================================================================
// K3: reduce 4 cov slices -> pcc row, then q/k projections. block per (c,b)
// =============================================================================
__global__ void __launch_bounds__(256) pccqk_kernel(const float* __restrict__ qw, const float* __restrict__ qb,
                                                    const float* __restrict__ kw, const float* __restrict__ kb){
    int c=blockIdx.x, b=blockIdx.y, tid=threadIdx.x;
    __shared__ float row[256];
    __shared__ float sp[64][4];
    __shared__ float sden;
    if(tid==0){
        float d=0.f;
        #pragma unroll
        for(int i=0;i<8;i++) d += g_varpart[b*8+i];
        sden = 1.0f/d;
    }
    size_t base = ((size_t)b*Cc + c)*Cc + tid;
    float v = g_covp[base] + g_covp[(size_t)SL + base]
            + g_covp[2*(size_t)SL + base] + g_covp[3*(size_t)SL + base];
    __syncthreads();
    row[tid] = v * sden;
    __syncthreads();
    int e = tid>>2, seg = tid&3;
    const float* w = (e<32) ? (qw + e*Cc) : (kw + (e-32)*Cc);
    float p=0.f;
    int d0 = seg*64;
    #pragma unroll 8
    for(int d=0; d<64; d++) p += row[d0+d]*__ldg(&w[d0+d]);
    sp[e][seg]=p;
    __syncthreads();
    if(tid<64){
        float r = sp[tid][0]+sp[tid][1]+sp[tid][2]+sp[tid][3];
        if(tid<32) g_q[((size_t)b*Cc+c)*32 + tid]      = r + qb[tid];
        else       g_k[((size_t)b*Cc+c)*32 + (tid-32)] = r + kb[tid-32];
    }
}

// =============================================================================
// K4: scores + softmax, warp-per-query (measured -19us vs per-query blocks).
// Block = (32 queries, b); grid (8, Bb). Writes attn to d_out (natural) and
// transposed g_attnT for the out-GEMM.
// =============================================================================
__global__ void __launch_bounds__(256) attn_kernel(float* __restrict__ out){
    int bg = blockIdx.x, b = blockIdx.y;
    int tid = threadIdx.x, w = tid>>5, lane = tid&31;
    __shared__ float ks[256][36];
    __shared__ float qs[32][36];
    const float* kp = g_k + (size_t)b*Cc*32;
    int c0 = bg*32;
    #pragma unroll
    for(int p=0;p<8;p++){
        int idx = tid + p*256;
        int d = idx>>3, e4 = (idx&7)*4;
        *(float4*)&ks[d][e4] = *(const float4*)&kp[d*32 + e4];
    }
    {
        int q = tid>>3, e4 = (tid&7)*4;
        *(float4*)&qs[q][e4] = *(const float4*)&g_q[((size_t)b*Cc + c0 + q)*32 + e4];
    }
    __syncthreads();
    float* ao = out + OUT_ELEMS + ((size_t)b*Cc + c0)*Cc;
    float* atT = g_attnT + (size_t)b*Cc*Cc;
    #pragma unroll
    for(int qi=0; qi<4; qi++){
        int q = w*4 + qi;
        float s[8];
        #pragma unroll
        for(int m=0;m<8;m++) s[m]=0.f;
        #pragma unroll
        for(int e4=0;e4<8;e4++){
            float4 qv = *(const float4*)&qs[q][e4*4];
            #pragma unroll
            for(int m=0;m<8;m++){
                float4 kv = *(const float4*)&ks[m*32+lane][e4*4];
                s[m] += qv.x*kv.x + qv.y*kv.y + qv.z*kv.z + qv.w*kv.w;
            }
        }
        float mx = s[0]*(1.0f/16.0f);
        #pragma unroll
        for(int m=0;m<8;m++){ s[m] *= (1.0f/16.0f); mx = fmaxf(mx, s[m]); }
        #pragma unroll
        for(int d=16; d>0; d>>=1) mx = fmaxf(mx, __shfl_xor_sync(0xffffffffu, mx, d));
        float ev[8], sm=0.f;
        #pragma unroll
        for(int m=0;m<8;m++){ ev[m] = expf(s[m]-mx); sm += ev[m]; }
        #pragma unroll
        for(int d=16; d>0; d>>=1) sm += __shfl_xor_sync(0xffffffffu, sm, d);
        float inv = 1.0f/sm;
        #pragma unroll
        for(int m=0;m<8;m++){
            float a = ev[m]*inv;
            ao[(size_t)q*Cc + m*32 + lane] = a;
            atT[(size_t)(m*32+lane)*Cc + c0 + q] = a;
        }
    }
}

// =============================================================================
// K5: out = attn @ x (EXACT R2 version — known-good). Tile 128(M) x 64(N),
// K=256 chunked by 32, k-major smem tiles, M-packed f32x2.
// =============================================================================
__global__ void __launch_bounds__(256) out_gemm(const float* __restrict__ x, float* __restrict__ out){
    int tb=blockIdx.x, cb=blockIdx.y, b=blockIdx.z;
    int t0 = tb*64, c0 = cb*128;
    __shared__ float As[32][128];   // attnT chunk: [k=d][c]
    __shared__ float Bs[32][64];    // x chunk:     [k=d][t]
    const float* at = g_attnT + (size_t)b*Cc*Cc;
    const float* xb = x + (size_t)b*Cc*Tt;
    int tid=threadIdx.x, ty=tid>>4, tx=tid&15;

    u64 acc[4][4];
    #pragma unroll
    for(int i=0;i<4;i++){
        #pragma unroll
        for(int j=0;j<4;j++) acc[i][j]=0ull;
    }

    for(int d0=0; d0<Cc; d0+=32){
        __syncthreads();
        #pragma unroll
        for(int p=0;p<4;p++){
            int idx = tid + p*256;
            int k = idx>>5, c4 = (idx&31)*4;
            *(float4*)&As[k][c4] = *(const float4*)&at[(size_t)(d0+k)*Cc + c0 + c4];
        }
        {
            int k = tid>>4, c4 = (tid&15)*4;
            *(float4*)&Bs[k   ][c4] = *(const float4*)&xb[(size_t)(d0+k   )*Tt + t0 + c4];
            *(float4*)&Bs[k+16][c4] = *(const float4*)&xb[(size_t)(d0+k+16)*Tt + t0 + c4];
        }
        __syncthreads();
        #pragma unroll
        for(int kk=0;kk<32;kk++){
            longlong2 aA = *(const longlong2*)&As[kk][ty*8];
            longlong2 aB = *(const longlong2*)&As[kk][ty*8+4];
            float4 bf = *(const float4*)&Bs[kk][tx*4];
            u64 b0=dup2(bf.x), b1=dup2(bf.y), b2=dup2(bf.z), b3=dup2(bf.w);
            fma2(acc[0][0],(u64)aA.x,b0); fma2(acc[0][1],(u64)aA.x,b1);
            fma2(acc[0][2],(u64)aA.x,b2); fma2(acc[0][3],(u64)aA.x,b3);
            fma2(acc[1][0],(u64)aA.y,b0); fma2(acc[1][1],(u64)aA.y,b1);
            fma2(acc[1][2],(u64)aA.y,b2); fma2(acc[1][3],(u64)aA.y,b3);
            fma2(acc[2][0],(u64)aB.x,b0); fma2(acc[2][1],(u64)aB.x,b1);
            fma2(acc[2][2],(u64)aB.x,b2); fma2(acc[2][3],(u64)aB.x,b3);
            fma2(acc[3][0],(u64)aB.y,b0); fma2(acc[3][1],(u64)aB.y,b1);
            fma2(acc[3][2],(u64)aB.y,b2); fma2(acc[3][3],(u64)aB.y,b3);
        }
    }

    float* ob = out + (size_t)b*Cc*Tt;
    #pragma unroll
    for(int i2=0;i2<4;i2++){
        float2 f0=unpk(acc[i2][0]), f1=unpk(acc[i2][1]), f2=unpk(acc[i2][2]), f3=unpk(acc[i2][3]);
        int r0 = c0 + ty*8 + i2*2;
        *(float4*)&ob[(size_t)r0    *Tt + t0 + tx*4] = make_float4(f0.x,f1.x,f2.x,f3.x);
        *(float4*)&ob[(size_t)(r0+1)*Tt + t0 + tx*4] = make_float4(f0.y,f1.y,f2.y,f3.y);
    }
}

// =============================================================================
extern "C" void kernel_launch(void* const* d_in, const int* in_sizes, int n_in,
                              void* d_out, int out_size){
    const float* x  = (const float*)d_in[0];
    const float* qw = (const float*)d_in[1];
    const float* qb = (const float*)d_in[2];
    const float* kw = (const float*)d_in[3];
    const float* kb = (const float*)d_in[4];
    float* out = (float*)d_out;

    stats_kernel<<<dim3(Tt/1024, Bb), 256>>>(x);
    cov_kernel  <<<dim3(10, Bb, KSPLIT), 256>>>(x);
    pccqk_kernel<<<dim3(Cc, Bb), 256>>>(qw, qb, kw, kb);
    attn_kernel <<<dim3(Cc/32, Bb), 256>>>(out);
    out_gemm    <<<dim3(Tt/64, Cc/128, Bb), 256>>>(x, out);
}

// round 9
// speedup vs baseline: 1.1286x; 1.0557x over previous
#include <cuda_runtime.h>
#include <math.h>

#define Bb 16
#define Cc 256
#define Tt 8192
#define KSPLIT 4
#define SL (Bb*Cc*Cc)
#define OUT_ELEMS ((size_t)Bb*Cc*Tt)

typedef unsigned long long u64;

// ---------------- scratch (static device globals; no allocation) -------------
__device__ float g_mean[Bb*Tt];
__device__ float g_varpart[Bb*32];
__device__ float g_covp[(size_t)KSPLIT*SL];
__device__ float g_attnT[(size_t)Bb*Cc*Cc];   // attn transposed [b][d][c]
__device__ float g_q[Bb*Cc*32];
__device__ float g_k[Bb*Cc*32];

// ---------------- f32x2 packed-FMA helpers (Blackwell) -----------------------
__device__ __forceinline__ void fma2(u64 &d, u64 a, u64 b){
    asm("fma.rn.f32x2 %0, %1, %2, %0;" : "+l"(d) : "l"(a), "l"(b));
}
__device__ __forceinline__ u64 dup2(float v){
    u64 r; asm("mov.b64 %0, {%1, %1};" : "=l"(r) : "f"(v)); return r;
}
__device__ __forceinline__ float2 unpk(u64 v){
    float2 f; asm("mov.b64 {%0, %1}, %2;" : "=f"(f.x), "=f"(f.y) : "l"(v)); return f;
}

// =============================================================================
// K1: per-(b,t) mean/var over C (EXACT R2 version — 512 blocks, known-good)
// =============================================================================
__global__ void __launch_bounds__(256) stats_kernel(const float* __restrict__ x){
    int b = blockIdx.y;
    int t = blockIdx.x*256 + threadIdx.x;
    const float* xp = x + (size_t)b*Cc*Tt + t;
    float s0=0.f,s1=0.f,q0=0.f,q1=0.f;
    #pragma unroll 4
    for(int c=0;c<Cc;c+=2){
        float v0 = xp[(size_t)c*Tt];
        float v1 = xp[(size_t)(c+1)*Tt];
        s0+=v0; q0+=v0*v0;
        s1+=v1; q1+=v1*v1;
    }
    float s=s0+s1, q=q0+q1;
    float mean = s*(1.0f/Cc);
    g_mean[b*Tt+t] = mean;
    float var = (q - s*mean)*(1.0f/(Cc-1));
    __shared__ float red[256];
    int tid = threadIdx.x;
    red[tid]=var; __syncthreads();
    for(int w=128;w>0;w>>=1){ if(tid<w) red[tid]+=red[tid+w]; __syncthreads(); }
    if(tid==0) g_varpart[b*32+blockIdx.x]=red[0];
}

// =============================================================================
// K2: cov partials (R2 structure + register prefetch of next chunk's LDGs).
// 10 upper 64x64 tiles, 4 K-slices, K-packed f32x2, XOR-swizzled smem.
// =============================================================================
__constant__ int c_ti[10]={0,0,0,0,1,1,1,2,2,3};
__constant__ int c_tj[10]={0,1,2,3,1,2,3,2,3,3};

__global__ void __launch_bounds__(256) cov_kernel(const float* __restrict__ x){
    int tile=blockIdx.x, b=blockIdx.y, sl=blockIdx.z;
    int i0=c_ti[tile]*64, j0=c_tj[tile]*64;
    bool diag=(i0==j0);
    __shared__ float As[64][32];
    __shared__ float Bs[64][32];
    const float* xb = x + (size_t)b*Cc*Tt;
    const float* mb = g_mean + b*Tt;
    int tid=threadIdx.x;
    int ty=tid>>4, tx=tid&15;
    int lr=tid>>3, lkf=tid&7;
    int sslot = ((lkf ^ ((lr>>2)&7))<<2);
    int swa = ty&7, swb = tx&7;

    u64 acc[4][4];
    #pragma unroll
    for(int i=0;i<4;i++){
        #pragma unroll
        for(int j=0;j<4;j++) acc[i][j]=0ull;
    }

    const int NCH = (Tt/KSPLIT)/32;
    int kbase = sl*(Tt/KSPLIT);
    float4 mv, a0, a1, b0, b1;

#define COV_LOAD(CH) { int kt = kbase + (CH)*32 + lkf*4;                        \
        mv = *(const float4*)&mb[kt];                                           \
        a0 = *(const float4*)&xb[(size_t)(i0+lr   )*Tt + kt];                   \
        a1 = *(const float4*)&xb[(size_t)(i0+lr+32)*Tt + kt];                   \
        if(!diag){                                                              \
            b0 = *(const float4*)&xb[(size_t)(j0+lr   )*Tt + kt];               \
            b1 = *(const float4*)&xb[(size_t)(j0+lr+32)*Tt + kt];               \
        } }

    COV_LOAD(0);
    #pragma unroll 1
    for(int ch=0; ch<NCH; ++ch){
        __syncthreads();
        *(float4*)&As[lr   ][sslot] = make_float4(a0.x-mv.x,a0.y-mv.y,a0.z-mv.z,a0.w-mv.w);
        *(float4*)&As[lr+32][sslot] = make_float4(a1.x-mv.x,a1.y-mv.y,a1.z-mv.z,a1.w-mv.w);
        if(!diag){
            *(float4*)&Bs[lr   ][sslot] = make_float4(b0.x-mv.x,b0.y-mv.y,b0.z-mv.z,b0.w-mv.w);
            *(float4*)&Bs[lr+32][sslot] = make_float4(b1.x-mv.x,b1.y-mv.y,b1.z-mv.z,b1.w-mv.w);
        }
        __syncthreads();
        if(ch+1<NCH) COV_LOAD(ch+1);   // LDGs fly during the FMA phase below
        float (*Bp)[32] = diag ? As : Bs;
        #pragma unroll
        for(int k4=0;k4<8;k4++){
            int sa = ((k4^swa)<<2);
            int sb = ((k4^swb)<<2);
            longlong2 av[4], bv[4];
            #pragma unroll
            for(int i=0;i<4;i++) av[i] = *(const longlong2*)&As[ty*4+i][sa];
            #pragma unroll
            for(int j=0;j<4;j++) bv[j] = *(const longlong2*)&Bp[tx*4+j][sb];
            #pragma unroll
            for(int i=0;i<4;i++){
                #pragma unroll
                for(int j=0;j<4;j++){
                    fma2(acc[i][j], (u64)av[i].x, (u64)bv[j].x);
                    fma2(acc[i][j], (u64)av[i].y, (u64)bv[j].y);
                }
            }
        }
    }
#undef COV_LOAD

    float* cp = g_covp + (size_t)(sl*Bb+b)*Cc*Cc;
    #pragma unroll
    for(int i=0;i<4;i++){
        float r[4];
        #pragma unroll
        for(int j=0;j<4;j++){ float2 f=unpk(acc[i][j]); r[j]=f.x+f.y; }
        int ci = i0+ty*4+i;
        *(float4*)&cp[(size_t)ci*Cc + j0 + tx*4] = make_float4(r[0],r[1],r[2],r[3]);
        if(!diag){
            #pragma unroll
            for(int j=0;j<4;j++) cp[(size_t)(j0+tx*4+j)*Cc + ci] = r[j];
        }
    }
}

// =============================================================================
// K3: reduce 4 cov slices -> pcc row, then q/k projections. block per (c,b)
// =============================================================================
__global__ void __launch_bounds__(256) pccqk_kernel(const float* __restrict__ qw, const float* __restrict__ qb,
                                                    const float* __restrict__ kw, const float* __restrict__ kb){
    int c=blockIdx.x, b=blockIdx.y, tid=threadIdx.x;
    __shared__ float row[256];
    __shared__ float sp[64][4];
    __shared__ float sden;
    if(tid==0){
        float d=0.f;
        #pragma unroll
        for(int i=0;i<32;i++) d += g_varpart[b*32+i];
        sden = 1.0f/d;
    }
    size_t base = ((size_t)b*Cc + c)*Cc + tid;
    float v = g_covp[base] + g_covp[(size_t)SL + base]
            + g_covp[2*(size_t)SL + base] + g_covp[3*(size_t)SL + base];
    __syncthreads();
    row[tid] = v * sden;
    __syncthreads();
    int e = tid>>2, seg = tid&3;
    const float* w = (e<32) ? (qw + e*Cc) : (kw + (e-32)*Cc);
    float p=0.f;
    int d0 = seg*64;
    #pragma unroll 8
    for(int d=0; d<64; d++) p += row[d0+d]*__ldg(&w[d0+d]);
    sp[e][seg]=p;
    __syncthreads();
    if(tid<64){
        float r = sp[tid][0]+sp[tid][1]+sp[tid][2]+sp[tid][3];
        if(tid<32) g_q[((size_t)b*Cc+c)*32 + tid]      = r + qb[tid];
        else       g_k[((size_t)b*Cc+c)*32 + (tid-32)] = r + kb[tid-32];
    }
}

// =============================================================================
// K4: scores + softmax, warp-per-query (measured win — keep from R8).
// =============================================================================
__global__ void __launch_bounds__(256) attn_kernel(float* __restrict__ out){
    int bg = blockIdx.x, b = blockIdx.y;
    int tid = threadIdx.x, w = tid>>5, lane = tid&31;
    __shared__ float ks[256][36];
    __shared__ float qs[32][36];
    const float* kp = g_k + (size_t)b*Cc*32;
    int c0 = bg*32;
    #pragma unroll
    for(int p=0;p<8;p++){
        int idx = tid + p*256;
        int d = idx>>3, e4 = (idx&7)*4;
        *(float4*)&ks[d][e4] = *(const float4*)&kp[d*32 + e4];
    }
    {
        int q = tid>>3, e4 = (tid&7)*4;
        *(float4*)&qs[q][e4] = *(const float4*)&g_q[((size_t)b*Cc + c0 + q)*32 + e4];
    }
    __syncthreads();
    float* ao = out + OUT_ELEMS + ((size_t)b*Cc + c0)*Cc;
    float* atT = g_attnT + (size_t)b*Cc*Cc;
    #pragma unroll
    for(int qi=0; qi<4; qi++){
        int q = w*4 + qi;
        float s[8];
        #pragma unroll
        for(int m=0;m<8;m++) s[m]=0.f;
        #pragma unroll
        for(int e4=0;e4<8;e4++){
            float4 qv = *(const float4*)&qs[q][e4*4];
            #pragma unroll
            for(int m=0;m<8;m++){
                float4 kv = *(const float4*)&ks[m*32+lane][e4*4];
                s[m] += qv.x*kv.x + qv.y*kv.y + qv.z*kv.z + qv.w*kv.w;
            }
        }
        float mx = s[0]*(1.0f/16.0f);
        #pragma unroll
        for(int m=0;m<8;m++){ s[m] *= (1.0f/16.0f); mx = fmaxf(mx, s[m]); }
        #pragma unroll
        for(int d=16; d>0; d>>=1) mx = fmaxf(mx, __shfl_xor_sync(0xffffffffu, mx, d));
        float ev[8], sm=0.f;
        #pragma unroll
        for(int m=0;m<8;m++){ ev[m] = expf(s[m]-mx); sm += ev[m]; }
        #pragma unroll
        for(int d=16; d>0; d>>=1) sm += __shfl_xor_sync(0xffffffffu, sm, d);
        float inv = 1.0f/sm;
        #pragma unroll
        for(int m=0;m<8;m++){
            float a = ev[m]*inv;
            ao[(size_t)q*Cc + m*32 + lane] = a;
            atT[(size_t)(m*32+lane)*Cc + c0 + q] = a;
        }
    }
}

// =============================================================================
// K5: out = attn @ x (R2 structure + register prefetch of next chunk's LDGs).
// Tile 128(M) x 64(N), K=256 chunked by 32, k-major smem, M-packed f32x2.
// =============================================================================
__global__ void __launch_bounds__(256) out_gemm(const float* __restrict__ x, float* __restrict__ out){
    int tb=blockIdx.x, cb=blockIdx.y, b=blockIdx.z;
    int t0 = tb*64, c0 = cb*128;
    __shared__ float As[32][128];   // attnT chunk: [k=d][c]
    __shared__ float Bs[32][64];    // x chunk:     [k=d][t]
    const float* at = g_attnT + (size_t)b*Cc*Cc;
    const float* xb = x + (size_t)b*Cc*Tt;
    int tid=threadIdx.x, ty=tid>>4, tx=tid&15;
    int ka = tid>>5, c4a = (tid&31)*4;        // As load mapping
    int kb2 = tid>>4, c4b = (tid&15)*4;       // Bs load mapping

    u64 acc[4][4];
    #pragma unroll
    for(int i=0;i<4;i++){
        #pragma unroll
        for(int j=0;j<4;j++) acc[i][j]=0ull;
    }

    float4 av0, av1, av2, av3, bw0, bw1;
#define OG_LOAD(D0) {                                                           \
        av0 = *(const float4*)&at[(size_t)((D0)+ka   )*Cc + c0 + c4a];           \
        av1 = *(const float4*)&at[(size_t)((D0)+ka+ 8)*Cc + c0 + c4a];           \
        av2 = *(const float4*)&at[(size_t)((D0)+ka+16)*Cc + c0 + c4a];           \
        av3 = *(const float4*)&at[(size_t)((D0)+ka+24)*Cc + c0 + c4a];           \
        bw0 = *(const float4*)&xb[(size_t)((D0)+kb2   )*Tt + t0 + c4b];          \
        bw1 = *(const float4*)&xb[(size_t)((D0)+kb2+16)*Tt + t0 + c4b]; }

    OG_LOAD(0);
    #pragma unroll 1
    for(int d0=0; d0<Cc; d0+=32){
        __syncthreads();
        *(float4*)&As[ka   ][c4a] = av0;
        *(float4*)&As[ka+ 8][c4a] = av1;
        *(float4*)&As[ka+16][c4a] = av2;
        *(float4*)&As[ka+24][c4a] = av3;
        *(float4*)&Bs[kb2   ][c4b] = bw0;
        *(float4*)&Bs[kb2+16][c4b] = bw1;
        __syncthreads();
        if(d0+32<Cc) OG_LOAD(d0+32);   // LDGs fly during the FMA phase below
        #pragma unroll
        for(int kk=0;kk<32;kk++){
            longlong2 aA = *(const longlong2*)&As[kk][ty*8];
            longlong2 aB = *(const longlong2*)&As[kk][ty*8+4];
            float4 bf = *(const float4*)&Bs[kk][tx*4];
            u64 b0=dup2(bf.x), b1=dup2(bf.y), b2=dup2(bf.z), b3=dup2(bf.w);
            fma2(acc[0][0],(u64)aA.x,b0); fma2(acc[0][1],(u64)aA.x,b1);
            fma2(acc[0][2],(u64)aA.x,b2); fma2(acc[0][3],(u64)aA.x,b3);
            fma2(acc[1][0],(u64)aA.y,b0); fma2(acc[1][1],(u64)aA.y,b1);
            fma2(acc[1][2],(u64)aA.y,b2); fma2(acc[1][3],(u64)aA.y,b3);
            fma2(acc[2][0],(u64)aB.x,b0); fma2(acc[2][1],(u64)aB.x,b1);
            fma2(acc[2][2],(u64)aB.x,b2); fma2(acc[2][3],(u64)aB.x,b3);
            fma2(acc[3][0],(u64)aB.y,b0); fma2(acc[3][1],(u64)aB.y,b1);
            fma2(acc[3][2],(u64)aB.y,b2); fma2(acc[3][3],(u64)aB.y,b3);
        }
    }
#undef OG_LOAD

    float* ob = out + (size_t)b*Cc*Tt;
    #pragma unroll
    for(int i2=0;i2<4;i2++){
        float2 f0=unpk(acc[i2][0]), f1=unpk(acc[i2][1]), f2=unpk(acc[i2][2]), f3=unpk(acc[i2][3]);
        int r0 = c0 + ty*8 + i2*2;
        *(float4*)&ob[(size_t)r0    *Tt + t0 + tx*4] = make_float4(f0.x,f1.x,f2.x,f3.x);
        *(float4*)&ob[(size_t)(r0+1)*Tt + t0 + tx*4] = make_float4(f0.y,f1.y,f2.y,f3.y);
    }
}

// =============================================================================
extern "C" void kernel_launch(void* const* d_in, const int* in_sizes, int n_in,
                              void* d_out, int out_size){
    const float* x  = (const float*)d_in[0];
    const float* qw = (const float*)d_in[1];
    const float* qb = (const float*)d_in[2];
    const float* kw = (const float*)d_in[3];
    const float* kb = (const float*)d_in[4];
    float* out = (float*)d_out;

    stats_kernel<<<dim3(Tt/256, Bb), 256>>>(x);
    cov_kernel  <<<dim3(10, Bb, KSPLIT), 256>>>(x);
    pccqk_kernel<<<dim3(Cc, Bb), 256>>>(qw, qb, kw, kb);
    attn_kernel <<<dim3(Cc/32, Bb), 256>>>(out);
    out_gemm    <<<dim3(Tt/64, Cc/128, Bb), 256>>>(x, out);
}

// round 11
// speedup vs baseline: 1.2403x; 1.0989x over previous
#include <cuda_runtime.h>
#include <cuda_bf16.h>
#include <math.h>

#define Bb 16
#define Cc 256
#define Tt 8192
#define KSPLIT 4
#define SL (Bb*Cc*Cc)
#define OUT_ELEMS ((size_t)Bb*Cc*Tt)

typedef unsigned long long u64;

// ---------------- scratch (static device globals; no allocation) -------------
__device__ float g_mean[Bb*Tt];
__device__ float g_varpart[Bb*32];
__device__ float g_covp[(size_t)KSPLIT*SL];
__device__ float g_q[Bb*Cc*32];
__device__ float g_k[Bb*Cc*32];
__device__ __nv_bfloat16 g_attn_h[(size_t)Bb*Cc*Cc];  // attn hi [b][c][d]
__device__ __nv_bfloat16 g_attn_l[(size_t)Bb*Cc*Cc];  // attn lo [b][c][d]

// ---------------- f32x2 helpers (for cov kernel) ----------------------------
__device__ __forceinline__ void fma2(u64 &d, u64 a, u64 b){
    asm("fma.rn.f32x2 %0, %1, %2, %0;" : "+l"(d) : "l"(a), "l"(b));
}
__device__ __forceinline__ float2 unpk(u64 v){
    float2 f; asm("mov.b64 {%0, %1}, %2;" : "=f"(f.x), "=f"(f.y) : "l"(v)); return f;
}

// ---------------- mma.sync helpers (sm_80+ ISA — compiles for compute_103) ---
__device__ __forceinline__ unsigned smem_u32(const void* p){
    unsigned a; asm("{ .reg .u64 t; cvta.to.shared.u64 t, %1; cvt.u32.u64 %0, t; }" : "=r"(a) : "l"(p)); return a;
}
__device__ __forceinline__ void cpasync16(unsigned dst, const void* src){
    asm volatile("cp.async.cg.shared.global [%0], [%1], 16;" :: "r"(dst), "l"(src));
}
__device__ __forceinline__ void ldsm_x4(unsigned* r, unsigned addr){
    asm volatile("ldmatrix.sync.aligned.m8n8.x4.shared.b16 {%0,%1,%2,%3}, [%4];"
        : "=r"(r[0]), "=r"(r[1]), "=r"(r[2]), "=r"(r[3]) : "r"(addr));
}
__device__ __forceinline__ void ldsm_x4_t(unsigned* r, unsigned addr){
    asm volatile("ldmatrix.sync.aligned.m8n8.x4.trans.shared.b16 {%0,%1,%2,%3}, [%4];"
        : "=r"(r[0]), "=r"(r[1]), "=r"(r[2]), "=r"(r[3]) : "r"(addr));
}
__device__ __forceinline__ void mma_bf16(float* d, const unsigned* a, const unsigned* b){
    asm volatile("mma.sync.aligned.m16n8k16.row.col.f32.bf16.bf16.f32 "
        "{%0,%1,%2,%3}, {%4,%5,%6,%7}, {%8,%9}, {%0,%1,%2,%3};"
        : "+f"(d[0]), "+f"(d[1]), "+f"(d[2]), "+f"(d[3])
        : "r"(a[0]), "r"(a[1]), "r"(a[2]), "r"(a[3]), "r"(b[0]), "r"(b[1]));
}

// =============================================================================
// K1: per-(b,t) mean/var over C (R2 version — known-good)
// =============================================================================
__global__ void __launch_bounds__(256) stats_kernel(const float* __restrict__ x){
    int b = blockIdx.y;
    int t = blockIdx.x*256 + threadIdx.x;
    const float* xp = x + (size_t)b*Cc*Tt + t;
    float s0=0.f,s1=0.f,q0=0.f,q1=0.f;
    #pragma unroll 4
    for(int c=0;c<Cc;c+=2){
        float v0 = xp[(size_t)c*Tt];
        float v1 = xp[(size_t)(c+1)*Tt];
        s0+=v0; q0+=v0*v0;
        s1+=v1; q1+=v1*v1;
    }
    float s=s0+s1, q=q0+q1;
    float mean = s*(1.0f/Cc);
    g_mean[b*Tt+t] = mean;
    float var = (q - s*mean)*(1.0f/(Cc-1));
    __shared__ float red[256];
    int tid = threadIdx.x;
    red[tid]=var; __syncthreads();
    for(int w=128;w>0;w>>=1){ if(tid<w) red[tid]+=red[tid+w]; __syncthreads(); }
    if(tid==0) g_varpart[b*32+blockIdx.x]=red[0];
}

// =============================================================================
// K2: cov partials (R9 version with prefetch — known-good)
// =============================================================================
__constant__ int c_ti[10]={0,0,0,0,1,1,1,2,2,3};
__constant__ int c_tj[10]={0,1,2,3,1,2,3,2,3,3};

__global__ void __launch_bounds__(256) cov_kernel(const float* __restrict__ x){
    int tile=blockIdx.x, b=blockIdx.y, sl=blockIdx.z;
    int i0=c_ti[tile]*64, j0=c_tj[tile]*64;
    bool diag=(i0==j0);
    __shared__ float As[64][32];
    __shared__ float Bs[64][32];
    const float* xb = x + (size_t)b*Cc*Tt;
    const float* mb = g_mean + b*Tt;
    int tid=threadIdx.x;
    int ty=tid>>4, tx=tid&15;
    int lr=tid>>3, lkf=tid&7;
    int sslot = ((lkf ^ ((lr>>2)&7))<<2);
    int swa = ty&7, swb = tx&7;

    u64 acc[4][4];
    #pragma unroll
    for(int i=0;i<4;i++){
        #pragma unroll
        for(int j=0;j<4;j++) acc[i][j]=0ull;
    }

    const int NCH = (Tt/KSPLIT)/32;
    int kbase = sl*(Tt/KSPLIT);
    float4 mv, a0, a1, b0, b1;

#define COV_LOAD(CH) { int kt = kbase + (CH)*32 + lkf*4;                        \
        mv = *(const float4*)&mb[kt];                                           \
        a0 = *(const float4*)&xb[(size_t)(i0+lr   )*Tt + kt];                   \
        a1 = *(const float4*)&xb[(size_t)(i0+lr+32)*Tt + kt];                   \
        if(!diag){                                                              \
            b0 = *(const float4*)&xb[(size_t)(j0+lr   )*Tt + kt];               \
            b1 = *(const float4*)&xb[(size_t)(j0+lr+32)*Tt + kt];               \
        } }

    COV_LOAD(0);
    #pragma unroll 1
    for(int ch=0; ch<NCH; ++ch){
        __syncthreads();
        *(float4*)&As[lr   ][sslot] = make_float4(a0.x-mv.x,a0.y-mv.y,a0.z-mv.z,a0.w-mv.w);
        *(float4*)&As[lr+32][sslot] = make_float4(a1.x-mv.x,a1.y-mv.y,a1.z-mv.z,a1.w-mv.w);
        if(!diag){
            *(float4*)&Bs[lr   ][sslot] = make_float4(b0.x-mv.x,b0.y-mv.y,b0.z-mv.z,b0.w-mv.w);
            *(float4*)&Bs[lr+32][sslot] = make_float4(b1.x-mv.x,b1.y-mv.y,b1.z-mv.z,b1.w-mv.w);
        }
        __syncthreads();
        if(ch+1<NCH) COV_LOAD(ch+1);
        float (*Bp)[32] = diag ? As : Bs;
        #pragma unroll
        for(int k4=0;k4<8;k4++){
            int sa = ((k4^swa)<<2);
            int sb = ((k4^swb)<<2);
            longlong2 av[4], bv[4];
            #pragma unroll
            for(int i=0;i<4;i++) av[i] = *(const longlong2*)&As[ty*4+i][sa];
            #pragma unroll
            for(int j=0;j<4;j++) bv[j] = *(const longlong2*)&Bp[tx*4+j][sb];
            #pragma unroll
            for(int i=0;i<4;i++){
                #pragma unroll
                for(int j=0;j<4;j++){
                    fma2(acc[i][j], (u64)av[i].x, (u64)bv[j].x);
                    fma2(acc[i][j], (u64)av[i].y, (u64)bv[j].y);
                }
            }
        }
    }
#undef COV_LOAD

    float* cp = g_covp + (size_t)(sl*Bb+b)*Cc*Cc;
    #pragma unroll
    for(int i=0;i<4;i++){
        float r[4];
        #pragma unroll
        for(int j=0;j<4;j++){ float2 f=unpk(acc[i][j]); r[j]=f.x+f.y; }
        int ci = i0+ty*4+i;
        *(float4*)&cp[(size_t)ci*Cc + j0 + tx*4] = make_float4(r[0],r[1],r[2],r[3]);
        if(!diag){
            #pragma unroll
            for(int j=0;j<4;j++) cp[(size_t)(j0+tx*4+j)*Cc + ci] = r[j];
        }
    }
}

// =============================================================================
// K3: reduce 4 cov slices -> pcc row, then q/k projections (unchanged)
// =============================================================================
__global__ void __launch_bounds__(256) pccqk_kernel(const float* __restrict__ qw, const float* __restrict__ qb,
                                                    const float* __restrict__ kw, const float* __restrict__ kb){
    int c=blockIdx.x, b=blockIdx.y, tid=threadIdx.x;
    __shared__ float row[256];
    __shared__ float sp[64][4];
    __shared__ float sden;
    if(tid==0){
        float d=0.f;
        #pragma unroll
        for(int i=0;i<32;i++) d += g_varpart[b*32+i];
        sden = 1.0f/d;
    }
    size_t base = ((size_t)b*Cc + c)*Cc + tid;
    float v = g_covp[base] + g_covp[(size_t)SL + base]
            + g_covp[2*(size_t)SL + base] + g_covp[3*(size_t)SL + base];
    __syncthreads();
    row[tid] = v * sden;
    __syncthreads();
    int e = tid>>2, seg = tid&3;
    const float* w = (e<32) ? (qw + e*Cc) : (kw + (e-32)*Cc);
    float p=0.f;
    int d0 = seg*64;
    #pragma unroll 8
    for(int d=0; d<64; d++) p += row[d0+d]*__ldg(&w[d0+d]);
    sp[e][seg]=p;
    __syncthreads();
    if(tid<64){
        float r = sp[tid][0]+sp[tid][1]+sp[tid][2]+sp[tid][3];
        if(tid<32) g_q[((size_t)b*Cc+c)*32 + tid]      = r + qb[tid];
        else       g_k[((size_t)b*Cc+c)*32 + (tid-32)] = r + kb[tid-32];
    }
}

// =============================================================================
// K4: scores + softmax, warp-per-query; emits attn fp32 (d_out) + bf16 hi/lo
// =============================================================================
__global__ void __launch_bounds__(256) attn_kernel(float* __restrict__ out){
    int bg = blockIdx.x, b = blockIdx.y;
    int tid = threadIdx.x, w = tid>>5, lane = tid&31;
    __shared__ float ks[256][36];
    __shared__ float qs[32][36];
    const float* kp = g_k + (size_t)b*Cc*32;
    int c0 = bg*32;
    #pragma unroll
    for(int p=0;p<8;p++){
        int idx = tid + p*256;
        int d = idx>>3, e4 = (idx&7)*4;
        *(float4*)&ks[d][e4] = *(const float4*)&kp[d*32 + e4];
    }
    {
        int q = tid>>3, e4 = (tid&7)*4;
        *(float4*)&qs[q][e4] = *(const float4*)&g_q[((size_t)b*Cc + c0 + q)*32 + e4];
    }
    __syncthreads();
    float* ao = out + OUT_ELEMS + ((size_t)b*Cc + c0)*Cc;
    #pragma unroll
    for(int qi=0; qi<4; qi++){
        int q = w*4 + qi;
        float s[8];
        #pragma unroll
        for(int m=0;m<8;m++) s[m]=0.f;
        #pragma unroll
        for(int e4=0;e4<8;e4++){
            float4 qv = *(const float4*)&qs[q][e4*4];
            #pragma unroll
            for(int m=0;m<8;m++){
                float4 kv = *(const float4*)&ks[m*32+lane][e4*4];
                s[m] += qv.x*kv.x + qv.y*kv.y + qv.z*kv.z + qv.w*kv.w;
            }
        }
        float mx = s[0]*(1.0f/16.0f);
        #pragma unroll
        for(int m=0;m<8;m++){ s[m] *= (1.0f/16.0f); mx = fmaxf(mx, s[m]); }
        #pragma unroll
        for(int d=16; d>0; d>>=1) mx = fmaxf(mx, __shfl_xor_sync(0xffffffffu, mx, d));
        float ev[8], sm=0.f;
        #pragma unroll
        for(int m=0;m<8;m++){ ev[m] = expf(s[m]-mx); sm += ev[m]; }
        #pragma unroll
        for(int d=16; d>0; d>>=1) sm += __shfl_xor_sync(0xffffffffu, sm, d);
        float inv = 1.0f/sm;
        #pragma unroll
        for(int m=0;m<8;m++){
            float a = ev[m]*inv;
            size_t idx = ((size_t)b*Cc + c0 + q)*Cc + m*32 + lane;
            ao[(size_t)q*Cc + m*32 + lane] = a;
            __nv_bfloat16 h = __float2bfloat16(a);
            g_attn_h[idx] = h;
            g_attn_l[idx] = __float2bfloat16(a - __bfloat162float(h));
        }
    }
}

// =============================================================================
// K5: out = attn @ x via mma.sync bf16x3 (sm_80 ISA — compiles for sm_103).
// CTA tile 128c x 128t; K=256 in 4 chunks of 64. A = attn hi/lo bf16
// cp.async'd into pad-144B rows; x cp.async'd fp32 -> stage, converted to
// bf16 hi/lo [k][t] pad-272B rows. Frags: ldmatrix.x4 (A), x4.trans (B).
// acc fp32 accumulates all 3 split terms: ah*xh + ah*xl + al*xh.
// =============================================================================
#define OG_AH 0                    // 128 x 72 bf16 = 18432 B
#define OG_AL 18432
#define OG_BH 36864                // 64 x 136 bf16 = 17408 B
#define OG_BL 54272
#define OG_ST 71680                // 64 x 132 fp32 = 33792 B
#define OG_SMEM (71680 + 33792)

__global__ void __launch_bounds__(256) out_gemm_mma(const float* __restrict__ x,
                                                    float* __restrict__ out){
    extern __shared__ char sm[];
    unsigned sb = smem_u32(sm);
    int tid = threadIdx.x, w = tid>>5, lane = tid&31;
    int t0 = blockIdx.x*128, c0 = blockIdx.y*128, b = blockIdx.z;
    const float* xb = x + (size_t)b*Cc*Tt;
    const __nv_bfloat16* ah = g_attn_h + (size_t)b*Cc*Cc;
    const __nv_bfloat16* al = g_attn_l + (size_t)b*Cc*Cc;
    int wc = w&3, wt = w>>2;          // warp tile: 32c x 64t

    float acc[2][8][4];
    #pragma unroll
    for(int i=0;i<2;i++)
        #pragma unroll
        for(int j=0;j<8;j++)
            #pragma unroll
            for(int r=0;r<4;r++) acc[i][j][r]=0.f;

    #pragma unroll 1
    for(int ch=0; ch<4; ++ch){
        int d0 = ch*64;
        if(ch>0) __syncthreads();     // prior mma done before overwriting smem

        // ---- cp.async: attn hi/lo bf16 -> A tiles (pad-144B rows) ----
        #pragma unroll
        for(int p=0;p<8;p++){
            int lin = p*256 + tid;    // 2048 x 16B
            int arr = lin>>10, r = (lin>>3)&127, u = lin&7;
            const __nv_bfloat16* src = (arr ? al : ah) + (size_t)(c0+r)*Cc + d0 + u*8;
            cpasync16(sb + (arr ? OG_AL : OG_AH) + r*144 + u*16, src);
        }
        // ---- cp.async: x fp32 chunk [64d][128t] -> stage (pad-528B rows) ----
        #pragma unroll
        for(int p=0;p<8;p++){
            int lin = p*256 + tid;    // 2048 x 16B
            int r = lin>>5, u = lin&31;
            cpasync16(sb + OG_ST + r*528 + u*16, &xb[(size_t)(d0+r)*Tt + t0 + u*4]);
        }
        asm volatile("cp.async.commit_group;" ::: "memory");
        asm volatile("cp.async.wait_group 0;" ::: "memory");
        __syncthreads();

        // ---- convert stage -> B hi/lo bf16 [k][t] (pad-272B rows) ----
        {
            int d = tid>>2, tg = tid&3;
            const float* sr = (const float*)(sm + OG_ST) + d*132 + tg*32;
            #pragma unroll
            for(int j=0;j<8;j++){
                float4 v = *(const float4*)&sr[j*4];
                float vv[4] = {v.x, v.y, v.z, v.w};
                unsigned hb[4], lb[4];
                #pragma unroll
                for(int i=0;i<4;i++){
                    __nv_bfloat16 h = __float2bfloat16(vv[i]);
                    __nv_bfloat16 l = __float2bfloat16(vv[i] - __bfloat162float(h));
                    hb[i] = __bfloat16_as_ushort(h);
                    lb[i] = __bfloat16_as_ushort(l);
                }
                int t = tg*32 + j*4;
                *(uint2*)(sm + OG_BH + d*272 + t*2) = make_uint2(hb[0]|(hb[1]<<16), hb[2]|(hb[3]<<16));
                *(uint2*)(sm + OG_BL + d*272 + t*2) = make_uint2(lb[0]|(lb[1]<<16), lb[2]|(lb[3]<<16));
            }
        }
        __syncthreads();

        // ---- mma phase: 4 k16 steps ----
        #pragma unroll
        for(int ks=0; ks<4; ks++){
            int k0 = ks*16;
            unsigned afh[2][4], afl[2][4];
            #pragma unroll
            for(int mt=0; mt<2; mt++){
                unsigned ra = sb + OG_AH + (unsigned)(wc*32 + mt*16 + (lane&15))*144
                            + k0*2 + ((lane>>4)<<4);
                ldsm_x4(afh[mt], ra);
                ldsm_x4(afl[mt], ra + (OG_AL - OG_AH));
            }
            unsigned bfh[4][4], bfl[4][4];
            int kk = k0 + (lane&7) + (((lane>>3)&1)<<3);
            #pragma unroll
            for(int ng=0; ng<4; ng++){
                int tt = wt*64 + ng*16 + (((lane>>4)&1)<<3);
                unsigned rb = sb + OG_BH + (unsigned)kk*272 + tt*2;
                ldsm_x4_t(bfh[ng], rb);
                ldsm_x4_t(bfl[ng], rb + (OG_BL - OG_BH));
            }
            #pragma unroll
            for(int mt=0; mt<2; mt++){
                #pragma unroll
                for(int ng=0; ng<4; ng++){
                    mma_bf16(acc[mt][ng*2  ], afh[mt], &bfh[ng][0]);
                    mma_bf16(acc[mt][ng*2  ], afh[mt], &bfl[ng][0]);
                    mma_bf16(acc[mt][ng*2  ], afl[mt], &bfh[ng][0]);
                    mma_bf16(acc[mt][ng*2+1], afh[mt], &bfh[ng][2]);
                    mma_bf16(acc[mt][ng*2+1], afh[mt], &bfl[ng][2]);
                    mma_bf16(acc[mt][ng*2+1], afl[mt], &bfh[ng][2]);
                }
            }
        }
    }

    // ---- epilogue: fragment layout d0,d1=(row, 2cols), d2,d3=(row+8) ----
    float* ob = out + (size_t)b*Cc*Tt;
    #pragma unroll
    for(int mt=0; mt<2; mt++){
        int r0 = c0 + wc*32 + mt*16 + (lane>>2);
        #pragma unroll
        for(int nt=0; nt<8; nt++){
            int t = t0 + wt*64 + nt*8 + (lane&3)*2;
            *(float2*)&ob[(size_t)r0*Tt + t]     = make_float2(acc[mt][nt][0], acc[mt][nt][1]);
            *(float2*)&ob[(size_t)(r0+8)*Tt + t] = make_float2(acc[mt][nt][2], acc[mt][nt][3]);
        }
    }
}

// =============================================================================
extern "C" void kernel_launch(void* const* d_in, const int* in_sizes, int n_in,
                              void* d_out, int out_size){
    const float* x  = (const float*)d_in[0];
    const float* qw = (const float*)d_in[1];
    const float* qb = (const float*)d_in[2];
    const float* kw = (const float*)d_in[3];
    const float* kb = (const float*)d_in[4];
    float* out = (float*)d_out;

    cudaFuncSetAttribute(out_gemm_mma, cudaFuncAttributeMaxDynamicSharedMemorySize, OG_SMEM);

    stats_kernel<<<dim3(Tt/256, Bb), 256>>>(x);
    cov_kernel  <<<dim3(10, Bb, KSPLIT), 256>>>(x);
    pccqk_kernel<<<dim3(Cc, Bb), 256>>>(qw, qb, kw, kb);
    attn_kernel <<<dim3(Cc/32, Bb), 256>>>(out);
    out_gemm_mma<<<dim3(Tt/128, Cc/128, Bb), 256, OG_SMEM>>>(x, out);
}

// round 12
// speedup vs baseline: 1.4594x; 1.1767x over previous
#include <cuda_runtime.h>
#include <cuda_bf16.h>
#include <math.h>

#define Bb 16
#define Cc 256
#define Tt 8192
#define KSPLIT 4
#define SL (Bb*Cc*Cc)
#define OUT_ELEMS ((size_t)Bb*Cc*Tt)

typedef unsigned long long u64;

// ---------------- scratch (static device globals; no allocation) -------------
__device__ float g_varpart[Bb*32];
__device__ float g_covp[(size_t)KSPLIT*SL];
__device__ float g_rs[Bb*Cc];
__device__ float g_S[Bb];
__device__ float g_den[Bb];
__device__ float g_q[Bb*Cc*32];
__device__ float g_k[Bb*Cc*32];
__device__ __nv_bfloat16 g_xh[(size_t)Bb*Cc*Tt];      // x hi bf16
__device__ __nv_bfloat16 g_xl[(size_t)Bb*Cc*Tt];      // x lo bf16
__device__ __nv_bfloat16 g_attn_h[(size_t)Bb*Cc*Cc];  // attn hi [b][c][d]
__device__ __nv_bfloat16 g_attn_l[(size_t)Bb*Cc*Cc];  // attn lo [b][c][d]

// ---------------- mma.sync helpers (sm_80+ ISA) ------------------------------
__device__ __forceinline__ unsigned smem_u32(const void* p){
    unsigned a; asm("{ .reg .u64 t; cvta.to.shared.u64 t, %1; cvt.u32.u64 %0, t; }" : "=r"(a) : "l"(p)); return a;
}
__device__ __forceinline__ void cpasync16(unsigned dst, const void* src){
    asm volatile("cp.async.cg.shared.global [%0], [%1], 16;" :: "r"(dst), "l"(src));
}
__device__ __forceinline__ void ldsm_x4(unsigned* r, unsigned addr){
    asm volatile("ldmatrix.sync.aligned.m8n8.x4.shared.b16 {%0,%1,%2,%3}, [%4];"
        : "=r"(r[0]), "=r"(r[1]), "=r"(r[2]), "=r"(r[3]) : "r"(addr));
}
__device__ __forceinline__ void ldsm_x4_t(unsigned* r, unsigned addr){
    asm volatile("ldmatrix.sync.aligned.m8n8.x4.trans.shared.b16 {%0,%1,%2,%3}, [%4];"
        : "=r"(r[0]), "=r"(r[1]), "=r"(r[2]), "=r"(r[3]) : "r"(addr));
}
__device__ __forceinline__ void mma_bf16(float* d, const unsigned* a, const unsigned* b){
    asm volatile("mma.sync.aligned.m16n8k16.row.col.f32.bf16.bf16.f32 "
        "{%0,%1,%2,%3}, {%4,%5,%6,%7}, {%8,%9}, {%0,%1,%2,%3};"
        : "+f"(d[0]), "+f"(d[1]), "+f"(d[2]), "+f"(d[3])
        : "r"(a[0]), "r"(a[1]), "r"(a[2]), "r"(a[3]), "r"(b[0]), "r"(b[1]));
}

// =============================================================================
// K1: per-(b,t) variance partials (ddof=1) + write x as bf16 hi/lo
// =============================================================================
__global__ void __launch_bounds__(256) stats_kernel(const float* __restrict__ x){
    int b = blockIdx.y;
    int t = blockIdx.x*256 + threadIdx.x;
    size_t base = (size_t)b*Cc*Tt + t;
    const float* xp = x + base;
    __nv_bfloat16* xh = g_xh + base;
    __nv_bfloat16* xl = g_xl + base;
    float s0=0.f,s1=0.f,q0=0.f,q1=0.f;
    #pragma unroll 4
    for(int c=0;c<Cc;c+=2){
        float v0 = xp[(size_t)c*Tt];
        float v1 = xp[(size_t)(c+1)*Tt];
        s0+=v0; q0+=v0*v0;
        s1+=v1; q1+=v1*v1;
        __nv_bfloat16 h0 = __float2bfloat16(v0);
        __nv_bfloat16 h1 = __float2bfloat16(v1);
        xh[(size_t)c*Tt]     = h0;
        xh[(size_t)(c+1)*Tt] = h1;
        xl[(size_t)c*Tt]     = __float2bfloat16(v0 - __bfloat162float(h0));
        xl[(size_t)(c+1)*Tt] = __float2bfloat16(v1 - __bfloat162float(h1));
    }
    float s=s0+s1, q=q0+q1;
    float mean = s*(1.0f/Cc);
    float var = (q - s*mean)*(1.0f/(Cc-1));
    __shared__ float red[256];
    int tid = threadIdx.x;
    red[tid]=var; __syncthreads();
    for(int w=128;w>0;w>>=1){ if(tid<w) red[tid]+=red[tid+w]; __syncthreads(); }
    if(tid==0) g_varpart[b*32+blockIdx.x]=red[0];
}

// =============================================================================
// K2: G = X X^T partials via mma.sync bf16x3. Tiles {(0,0),(0,1),(1,1)} of
// 128x128; K split by 4 (2048 per slice, 32 chunks of 64). Both operands
// [c][k] k-major in pad-144B rows; A and B use non-trans ldmatrix.
// Double-buffered cp.async (wait_group 1). Diag tiles reuse A buffers.
// =============================================================================
__constant__ int t2_i[3]={0,0,1};
__constant__ int t2_j[3]={0,1,1};

#define CV_TB   18432              // one 128 x 72bf16 tile (144 B rows)
#define CV_BUF  73728              // 4 tiles (AH, AL, BH, BL)
#define CV_SMEM (2*CV_BUF)         // 147456 B

__device__ __forceinline__ void cov_issue(unsigned sb, int buf, int kg, int i0, int j0,
                                          bool diag, int tid,
                                          const __nv_bfloat16* xh, const __nv_bfloat16* xl){
    #pragma unroll
    for(int p=0;p<8;p++){
        int lin = p*256 + tid;               // 2048 x 16B (AH + AL)
        int arr = lin>>10, r = (lin>>3)&127, u = lin&7;
        const __nv_bfloat16* s = (arr ? xl : xh) + (size_t)(i0+r)*Tt + kg + u*8;
        cpasync16(sb + buf*CV_BUF + arr*CV_TB + r*144 + u*16, s);
    }
    if(!diag){
        #pragma unroll
        for(int p=0;p<8;p++){
            int lin = p*256 + tid;           // BH + BL
            int arr = lin>>10, r = (lin>>3)&127, u = lin&7;
            const __nv_bfloat16* s = (arr ? xl : xh) + (size_t)(j0+r)*Tt + kg + u*8;
            cpasync16(sb + buf*CV_BUF + 2*CV_TB + arr*CV_TB + r*144 + u*16, s);
        }
    }
    asm volatile("cp.async.commit_group;" ::: "memory");
}

__global__ void __launch_bounds__(256) cov_mma(){
    extern __shared__ char sm[];
    unsigned sb = smem_u32(sm);
    int tid = threadIdx.x, w = tid>>5, lane = tid&31;
    int tile = blockIdx.x, b = blockIdx.y, sl = blockIdx.z;
    int i0 = t2_i[tile]*128, j0 = t2_j[tile]*128;
    bool diag = (i0==j0);
    int wc = w&3, wt = w>>2;                 // warp tile 32(i) x 64(j)
    const __nv_bfloat16* xh = g_xh + (size_t)b*Cc*Tt;
    const __nv_bfloat16* xl = g_xl + (size_t)b*Cc*Tt;
    int kbase = sl*(Tt/KSPLIT);
    const int NCH = (Tt/KSPLIT)/64;          // 32

    float acc[2][8][4];
    #pragma unroll
    for(int i=0;i<2;i++)
        #pragma unroll
        for(int j=0;j<8;j++)
            #pragma unroll
            for(int r=0;r<4;r++) acc[i][j][r]=0.f;

    cov_issue(sb, 0, kbase,      i0, j0, diag, tid, xh, xl);
    cov_issue(sb, 1, kbase+64,   i0, j0, diag, tid, xh, xl);

    #pragma unroll 1
    for(int ch=0; ch<NCH; ++ch){
        int buf = ch&1;
        asm volatile("cp.async.wait_group 1;" ::: "memory");
        __syncthreads();
        unsigned abase = sb + buf*CV_BUF;
        unsigned bbase = abase + (diag ? 0u : 2u*CV_TB);
        #pragma unroll
        for(int ks=0; ks<4; ks++){
            unsigned afh[2][4], afl[2][4];
            #pragma unroll
            for(int mt=0; mt<2; mt++){
                unsigned ra = abase + (unsigned)(wc*32 + mt*16 + (lane&15))*144
                            + ((lane>>4)<<4) + ks*32;
                ldsm_x4(afh[mt], ra);
                ldsm_x4(afl[mt], ra + CV_TB);
            }
            #pragma unroll
            for(int ng=0; ng<4; ng++){
                unsigned bfh[4], bfl[4];
                unsigned rb = bbase + (unsigned)(wt*64 + ng*16 + ((lane>>4)<<3) + (lane&7))*144
                            + (((lane>>3)&1)<<4) + ks*32;
                ldsm_x4(bfh, rb);
                ldsm_x4(bfl, rb + CV_TB);
                #pragma unroll
                for(int mt=0; mt<2; mt++){
                    mma_bf16(acc[mt][ng*2  ], afh[mt], &bfh[0]);
                    mma_bf16(acc[mt][ng*2  ], afh[mt], &bfl[0]);
                    mma_bf16(acc[mt][ng*2  ], afl[mt], &bfh[0]);
                    mma_bf16(acc[mt][ng*2+1], afh[mt], &bfh[2]);
                    mma_bf16(acc[mt][ng*2+1], afh[mt], &bfl[2]);
                    mma_bf16(acc[mt][ng*2+1], afl[mt], &bfh[2]);
                }
            }
        }
        __syncthreads();
        if(ch+2<NCH) cov_issue(sb, buf, kbase + (ch+2)*64, i0, j0, diag, tid, xh, xl);
    }

    float* cp = g_covp + ((size_t)sl*Bb + b)*Cc*Cc;
    #pragma unroll
    for(int mt=0; mt<2; mt++){
        int r0 = i0 + wc*32 + mt*16 + (lane>>2);
        #pragma unroll
        for(int nt=0; nt<8; nt++){
            int co = j0 + wt*64 + nt*8 + (lane&3)*2;
            *(float2*)&cp[(size_t)r0*Cc + co]     = make_float2(acc[mt][nt][0], acc[mt][nt][1]);
            *(float2*)&cp[(size_t)(r0+8)*Cc + co] = make_float2(acc[mt][nt][2], acc[mt][nt][3]);
            if(!diag){
                cp[(size_t)co*Cc + r0]       = acc[mt][nt][0];
                cp[(size_t)(co+1)*Cc + r0]   = acc[mt][nt][1];
                cp[(size_t)co*Cc + r0+8]     = acc[mt][nt][2];
                cp[(size_t)(co+1)*Cc + r0+8] = acc[mt][nt][3];
            }
        }
    }
}

// =============================================================================
// K2b: row sums of G (4 slices summed), total S, and 1/denom per batch.
// =============================================================================
__global__ void __launch_bounds__(256) rowsum_kernel(){
    int b = blockIdx.x, tid = threadIdx.x, w = tid>>5, lane = tid&31;
    __shared__ float srs[256];
    __shared__ float red[256];
    #pragma unroll 1
    for(int r = w; r < Cc; r += 8){
        float s = 0.f;
        #pragma unroll
        for(int sl=0; sl<4; sl++){
            const float* rp = g_covp + ((size_t)sl*Bb + b)*Cc*Cc + (size_t)r*Cc;
            #pragma unroll
            for(int j=0;j<8;j++) s += rp[j*32 + lane];
        }
        #pragma unroll
        for(int d=16; d>0; d>>=1) s += __shfl_xor_sync(0xffffffffu, s, d);
        if(lane==0){ srs[r]=s; g_rs[b*Cc+r]=s; }
    }
    __syncthreads();
    red[tid]=srs[tid]; __syncthreads();
    for(int v=128;v>0;v>>=1){ if(tid<v) red[tid]+=red[tid+v]; __syncthreads(); }
    if(tid==0){
        g_S[b]=red[0];
        float d=0.f;
        #pragma unroll
        for(int i=0;i<32;i++) d += g_varpart[b*32+i];
        g_den[b]=1.0f/d;
    }
}

// =============================================================================
// K3: pcc row from G + corrections, then q/k projections. block per (c,b)
// cov_ij = G_ij - (rs_i + rs_j)/C + S/C^2
// =============================================================================
__global__ void __launch_bounds__(256) pccqk_kernel(const float* __restrict__ qw, const float* __restrict__ qb,
                                                    const float* __restrict__ kw, const float* __restrict__ kb){
    int c=blockIdx.x, b=blockIdx.y, tid=threadIdx.x;
    __shared__ float row[256];
    __shared__ float sp[64][4];
    float sden = g_den[b];
    float Sc   = g_S[b]*(1.0f/((float)Cc*(float)Cc));
    float rs_c = g_rs[b*Cc+c]*(1.0f/Cc);
    float rs_j = g_rs[b*Cc+tid]*(1.0f/Cc);
    size_t base = ((size_t)b*Cc + c)*Cc + tid;
    float v = g_covp[base] + g_covp[(size_t)SL + base]
            + g_covp[2*(size_t)SL + base] + g_covp[3*(size_t)SL + base];
    row[tid] = (v - rs_c - rs_j + Sc) * sden;
    __syncthreads();
    int e = tid>>2, seg = tid&3;
    const float* w = (e<32) ? (qw + e*Cc) : (kw + (e-32)*Cc);
    float p=0.f;
    int d0 = seg*64;
    #pragma unroll 8
    for(int d=0; d<64; d++) p += row[d0+d]*__ldg(&w[d0+d]);
    sp[e][seg]=p;
    __syncthreads();
    if(tid<64){
        float r = sp[tid][0]+sp[tid][1]+sp[tid][2]+sp[tid][3];
        if(tid<32) g_q[((size_t)b*Cc+c)*32 + tid]      = r + qb[tid];
        else       g_k[((size_t)b*Cc+c)*32 + (tid-32)] = r + kb[tid-32];
    }
}

// =============================================================================
// K4: scores + softmax, warp-per-query; emits attn fp32 (d_out) + bf16 hi/lo
// =============================================================================
__global__ void __launch_bounds__(256) attn_kernel(float* __restrict__ out){
    int bg = blockIdx.x, b = blockIdx.y;
    int tid = threadIdx.x, w = tid>>5, lane = tid&31;
    __shared__ float ks[256][36];
    __shared__ float qs[32][36];
    const float* kp = g_k + (size_t)b*Cc*32;
    int c0 = bg*32;
    #pragma unroll
    for(int p=0;p<8;p++){
        int idx = tid + p*256;
        int d = idx>>3, e4 = (idx&7)*4;
        *(float4*)&ks[d][e4] = *(const float4*)&kp[d*32 + e4];
    }
    {
        int q = tid>>3, e4 = (tid&7)*4;
        *(float4*)&qs[q][e4] = *(const float4*)&g_q[((size_t)b*Cc + c0 + q)*32 + e4];
    }
    __syncthreads();
    float* ao = out + OUT_ELEMS + ((size_t)b*Cc + c0)*Cc;
    #pragma unroll
    for(int qi=0; qi<4; qi++){
        int q = w*4 + qi;
        float s[8];
        #pragma unroll
        for(int m=0;m<8;m++) s[m]=0.f;
        #pragma unroll
        for(int e4=0;e4<8;e4++){
            float4 qv = *(const float4*)&qs[q][e4*4];
            #pragma unroll
            for(int m=0;m<8;m++){
                float4 kv = *(const float4*)&ks[m*32+lane][e4*4];
                s[m] += qv.x*kv.x + qv.y*kv.y + qv.z*kv.z + qv.w*kv.w;
            }
        }
        float mx = s[0]*(1.0f/16.0f);
        #pragma unroll
        for(int m=0;m<8;m++){ s[m] *= (1.0f/16.0f); mx = fmaxf(mx, s[m]); }
        #pragma unroll
        for(int d=16; d>0; d>>=1) mx = fmaxf(mx, __shfl_xor_sync(0xffffffffu, mx, d));
        float ev[8], sm=0.f;
        #pragma unroll
        for(int m=0;m<8;m++){ ev[m] = expf(s[m]-mx); sm += ev[m]; }
        #pragma unroll
        for(int d=16; d>0; d>>=1) sm += __shfl_xor_sync(0xffffffffu, sm, d);
        float inv = 1.0f/sm;
        #pragma unroll
        for(int m=0;m<8;m++){
            float a = ev[m]*inv;
            size_t idx = ((size_t)b*Cc + c0 + q)*Cc + m*32 + lane;
            ao[(size_t)q*Cc + m*32 + lane] = a;
            __nv_bfloat16 h = __float2bfloat16(a);
            g_attn_h[idx] = h;
            g_attn_l[idx] = __float2bfloat16(a - __bfloat162float(h));
        }
    }
}

// =============================================================================
// K5: out = attn @ x via mma.sync bf16x3 (EXACT R11 version — known-good).
// =============================================================================
#define OG_AH 0
#define OG_AL 18432
#define OG_BH 36864
#define OG_BL 54272
#define OG_ST 71680
#define OG_SMEM (71680 + 33792)

__global__ void __launch_bounds__(256) out_gemm_mma(const float* __restrict__ x,
                                                    float* __restrict__ out){
    extern __shared__ char sm[];
    unsigned sb = smem_u32(sm);
    int tid = threadIdx.x, w = tid>>5, lane = tid&31;
    int t0 = blockIdx.x*128, c0 = blockIdx.y*128, b = blockIdx.z;
    const float* xb = x + (size_t)b*Cc*Tt;
    const __nv_bfloat16* ah = g_attn_h + (size_t)b*Cc*Cc;
    const __nv_bfloat16* al = g_attn_l + (size_t)b*Cc*Cc;
    int wc = w&3, wt = w>>2;

    float acc[2][8][4];
    #pragma unroll
    for(int i=0;i<2;i++)
        #pragma unroll
        for(int j=0;j<8;j++)
            #pragma unroll
            for(int r=0;r<4;r++) acc[i][j][r]=0.f;

    #pragma unroll 1
    for(int ch=0; ch<4; ++ch){
        int d0 = ch*64;
        if(ch>0) __syncthreads();

        #pragma unroll
        for(int p=0;p<8;p++){
            int lin = p*256 + tid;
            int arr = lin>>10, r = (lin>>3)&127, u = lin&7;
            const __nv_bfloat16* src = (arr ? al : ah) + (size_t)(c0+r)*Cc + d0 + u*8;
            cpasync16(sb + (arr ? OG_AL : OG_AH) + r*144 + u*16, src);
        }
        #pragma unroll
        for(int p=0;p<8;p++){
            int lin = p*256 + tid;
            int r = lin>>5, u = lin&31;
            cpasync16(sb + OG_ST + r*528 + u*16, &xb[(size_t)(d0+r)*Tt + t0 + u*4]);
        }
        asm volatile("cp.async.commit_group;" ::: "memory");
        asm volatile("cp.async.wait_group 0;" ::: "memory");
        __syncthreads();

        {
            int d = tid>>2, tg = tid&3;
            const float* sr = (const float*)(sm + OG_ST) + d*132 + tg*32;
            #pragma unroll
            for(int j=0;j<8;j++){
                float4 v = *(const float4*)&sr[j*4];
                float vv[4] = {v.x, v.y, v.z, v.w};
                unsigned hb[4], lb[4];
                #pragma unroll
                for(int i=0;i<4;i++){
                    __nv_bfloat16 h = __float2bfloat16(vv[i]);
                    __nv_bfloat16 l = __float2bfloat16(vv[i] - __bfloat162float(h));
                    hb[i] = __bfloat16_as_ushort(h);
                    lb[i] = __bfloat16_as_ushort(l);
                }
                int t = tg*32 + j*4;
                *(uint2*)(sm + OG_BH + d*272 + t*2) = make_uint2(hb[0]|(hb[1]<<16), hb[2]|(hb[3]<<16));
                *(uint2*)(sm + OG_BL + d*272 + t*2) = make_uint2(lb[0]|(lb[1]<<16), lb[2]|(lb[3]<<16));
            }
        }
        __syncthreads();

        #pragma unroll
        for(int ks=0; ks<4; ks++){
            int k0 = ks*16;
            unsigned afh[2][4], afl[2][4];
            #pragma unroll
            for(int mt=0; mt<2; mt++){
                unsigned ra = sb + OG_AH + (unsigned)(wc*32 + mt*16 + (lane&15))*144
                            + k0*2 + ((lane>>4)<<4);
                ldsm_x4(afh[mt], ra);
                ldsm_x4(afl[mt], ra + (OG_AL - OG_AH));
            }
            unsigned bfh[4][4], bfl[4][4];
            int kk = k0 + (lane&7) + (((lane>>3)&1)<<3);
            #pragma unroll
            for(int ng=0; ng<4; ng++){
                int tt = wt*64 + ng*16 + (((lane>>4)&1)<<3);
                unsigned rb = sb + OG_BH + (unsigned)kk*272 + tt*2;
                ldsm_x4_t(bfh[ng], rb);
                ldsm_x4_t(bfl[ng], rb + (OG_BL - OG_BH));
            }
            #pragma unroll
            for(int mt=0; mt<2; mt++){
                #pragma unroll
                for(int ng=0; ng<4; ng++){
                    mma_bf16(acc[mt][ng*2  ], afh[mt], &bfh[ng][0]);
                    mma_bf16(acc[mt][ng*2  ], afh[mt], &bfl[ng][0]);
                    mma_bf16(acc[mt][ng*2  ], afl[mt], &bfh[ng][0]);
                    mma_bf16(acc[mt][ng*2+1], afh[mt], &bfh[ng][2]);
                    mma_bf16(acc[mt][ng*2+1], afh[mt], &bfl[ng][2]);
                    mma_bf16(acc[mt][ng*2+1], afl[mt], &bfh[ng][2]);
                }
            }
        }
    }

    float* ob = out + (size_t)b*Cc*Tt;
    #pragma unroll
    for(int mt=0; mt<2; mt++){
        int r0 = c0 + wc*32 + mt*16 + (lane>>2);
        #pragma unroll
        for(int nt=0; nt<8; nt++){
            int t = t0 + wt*64 + nt*8 + (lane&3)*2;
            *(float2*)&ob[(size_t)r0*Tt + t]     = make_float2(acc[mt][nt][0], acc[mt][nt][1]);
            *(float2*)&ob[(size_t)(r0+8)*Tt + t] = make_float2(acc[mt][nt][2], acc[mt][nt][3]);
        }
    }
}

// =============================================================================
extern "C" void kernel_launch(void* const* d_in, const int* in_sizes, int n_in,
                              void* d_out, int out_size){
    const float* x  = (const float*)d_in[0];
    const float* qw = (const float*)d_in[1];
    const float* qb = (const float*)d_in[2];
    const float* kw = (const float*)d_in[3];
    const float* kb = (const float*)d_in[4];
    float* out = (float*)d_out;

    cudaFuncSetAttribute(out_gemm_mma, cudaFuncAttributeMaxDynamicSharedMemorySize, OG_SMEM);
    cudaFuncSetAttribute(cov_mma, cudaFuncAttributeMaxDynamicSharedMemorySize, CV_SMEM);

    stats_kernel <<<dim3(Tt/256, Bb), 256>>>(x);
    cov_mma      <<<dim3(3, Bb, KSPLIT), 256, CV_SMEM>>>();
    rowsum_kernel<<<Bb, 256>>>();
    pccqk_kernel <<<dim3(Cc, Bb), 256>>>(qw, qb, kw, kb);
    attn_kernel  <<<dim3(Cc/32, Bb), 256>>>(out);
    out_gemm_mma <<<dim3(Tt/128, Cc/128, Bb), 256, OG_SMEM>>>(x, out);
}

// round 13
// speedup vs baseline: 2.2314x; 1.5290x over previous
#include <cuda_runtime.h>
#include <cuda_bf16.h>
#include <math.h>

#define Bb 16
#define Cc 256
#define Tt 8192
#define KSPLIT 4
#define SL (Bb*Cc*Cc)
#define OUT_ELEMS ((size_t)Bb*Cc*Tt)

typedef unsigned long long u64;

// ---------------- scratch (static device globals; no allocation) -------------
__device__ float g_varpart[Bb*32];
__device__ float g_covp[(size_t)KSPLIT*SL];
__device__ float g_rs[Bb*Cc];
__device__ float g_q[Bb*Cc*32];
__device__ float g_k[Bb*Cc*32];
__device__ __nv_bfloat16 g_xh[(size_t)Bb*Cc*Tt];      // x hi bf16
__device__ __nv_bfloat16 g_xl[(size_t)Bb*Cc*Tt];      // x lo bf16
__device__ __nv_bfloat16 g_attn_h[(size_t)Bb*Cc*Cc];  // attn hi [b][c][d]
__device__ __nv_bfloat16 g_attn_l[(size_t)Bb*Cc*Cc];  // attn lo [b][c][d]

// ---------------- mma.sync helpers (sm_80+ ISA) ------------------------------
__device__ __forceinline__ unsigned smem_u32(const void* p){
    unsigned a; asm("{ .reg .u64 t; cvta.to.shared.u64 t, %1; cvt.u32.u64 %0, t; }" : "=r"(a) : "l"(p)); return a;
}
__device__ __forceinline__ void cpasync16(unsigned dst, const void* src){
    asm volatile("cp.async.cg.shared.global [%0], [%1], 16;" :: "r"(dst), "l"(src));
}
__device__ __forceinline__ void ldsm_x4(unsigned* r, unsigned addr){
    asm volatile("ldmatrix.sync.aligned.m8n8.x4.shared.b16 {%0,%1,%2,%3}, [%4];"
        : "=r"(r[0]), "=r"(r[1]), "=r"(r[2]), "=r"(r[3]) : "r"(addr));
}
__device__ __forceinline__ void ldsm_x4_t(unsigned* r, unsigned addr){
    asm volatile("ldmatrix.sync.aligned.m8n8.x4.trans.shared.b16 {%0,%1,%2,%3}, [%4];"
        : "=r"(r[0]), "=r"(r[1]), "=r"(r[2]), "=r"(r[3]) : "r"(addr));
}
__device__ __forceinline__ void mma_bf16(float* d, const unsigned* a, const unsigned* b){
    asm volatile("mma.sync.aligned.m16n8k16.row.col.f32.bf16.bf16.f32 "
        "{%0,%1,%2,%3}, {%4,%5,%6,%7}, {%8,%9}, {%0,%1,%2,%3};"
        : "+f"(d[0]), "+f"(d[1]), "+f"(d[2]), "+f"(d[3])
        : "r"(a[0]), "r"(a[1]), "r"(a[2]), "r"(a[3]), "r"(b[0]), "r"(b[1]));
}

// =============================================================================
// K1: per-(b,t) variance partials (ddof=1) + write x as bf16 hi/lo (R12)
// =============================================================================
__global__ void __launch_bounds__(256) stats_kernel(const float* __restrict__ x){
    int b = blockIdx.y;
    int t = blockIdx.x*256 + threadIdx.x;
    size_t base = (size_t)b*Cc*Tt + t;
    const float* xp = x + base;
    __nv_bfloat16* xh = g_xh + base;
    __nv_bfloat16* xl = g_xl + base;
    float s0=0.f,s1=0.f,q0=0.f,q1=0.f;
    #pragma unroll 4
    for(int c=0;c<Cc;c+=2){
        float v0 = xp[(size_t)c*Tt];
        float v1 = xp[(size_t)(c+1)*Tt];
        s0+=v0; q0+=v0*v0;
        s1+=v1; q1+=v1*v1;
        __nv_bfloat16 h0 = __float2bfloat16(v0);
        __nv_bfloat16 h1 = __float2bfloat16(v1);
        xh[(size_t)c*Tt]     = h0;
        xh[(size_t)(c+1)*Tt] = h1;
        xl[(size_t)c*Tt]     = __float2bfloat16(v0 - __bfloat162float(h0));
        xl[(size_t)(c+1)*Tt] = __float2bfloat16(v1 - __bfloat162float(h1));
    }
    float s=s0+s1, q=q0+q1;
    float mean = s*(1.0f/Cc);
    float var = (q - s*mean)*(1.0f/(Cc-1));
    __shared__ float red[256];
    int tid = threadIdx.x;
    red[tid]=var; __syncthreads();
    for(int w=128;w>0;w>>=1){ if(tid<w) red[tid]+=red[tid+w]; __syncthreads(); }
    if(tid==0) g_varpart[b*32+blockIdx.x]=red[0];
}

// =============================================================================
// K2: G = X X^T partials via mma.sync bf16x3 (EXACT R12 — known-good)
// =============================================================================
__constant__ int t2_i[3]={0,0,1};
__constant__ int t2_j[3]={0,1,1};

#define CV_TB   18432
#define CV_BUF  73728
#define CV_SMEM (2*CV_BUF)

__device__ __forceinline__ void cov_issue(unsigned sb, int buf, int kg, int i0, int j0,
                                          bool diag, int tid,
                                          const __nv_bfloat16* xh, const __nv_bfloat16* xl){
    #pragma unroll
    for(int p=0;p<8;p++){
        int lin = p*256 + tid;
        int arr = lin>>10, r = (lin>>3)&127, u = lin&7;
        const __nv_bfloat16* s = (arr ? xl : xh) + (size_t)(i0+r)*Tt + kg + u*8;
        cpasync16(sb + buf*CV_BUF + arr*CV_TB + r*144 + u*16, s);
    }
    if(!diag){
        #pragma unroll
        for(int p=0;p<8;p++){
            int lin = p*256 + tid;
            int arr = lin>>10, r = (lin>>3)&127, u = lin&7;
            const __nv_bfloat16* s = (arr ? xl : xh) + (size_t)(j0+r)*Tt + kg + u*8;
            cpasync16(sb + buf*CV_BUF + 2*CV_TB + arr*CV_TB + r*144 + u*16, s);
        }
    }
    asm volatile("cp.async.commit_group;" ::: "memory");
}

__global__ void __launch_bounds__(256) cov_mma(){
    extern __shared__ char sm[];
    unsigned sb = smem_u32(sm);
    int tid = threadIdx.x, w = tid>>5, lane = tid&31;
    int tile = blockIdx.x, b = blockIdx.y, sl = blockIdx.z;
    int i0 = t2_i[tile]*128, j0 = t2_j[tile]*128;
    bool diag = (i0==j0);
    int wc = w&3, wt = w>>2;
    const __nv_bfloat16* xh = g_xh + (size_t)b*Cc*Tt;
    const __nv_bfloat16* xl = g_xl + (size_t)b*Cc*Tt;
    int kbase = sl*(Tt/KSPLIT);
    const int NCH = (Tt/KSPLIT)/64;

    float acc[2][8][4];
    #pragma unroll
    for(int i=0;i<2;i++)
        #pragma unroll
        for(int j=0;j<8;j++)
            #pragma unroll
            for(int r=0;r<4;r++) acc[i][j][r]=0.f;

    cov_issue(sb, 0, kbase,    i0, j0, diag, tid, xh, xl);
    cov_issue(sb, 1, kbase+64, i0, j0, diag, tid, xh, xl);

    #pragma unroll 1
    for(int ch=0; ch<NCH; ++ch){
        int buf = ch&1;
        asm volatile("cp.async.wait_group 1;" ::: "memory");
        __syncthreads();
        unsigned abase = sb + buf*CV_BUF;
        unsigned bbase = abase + (diag ? 0u : 2u*CV_TB);
        #pragma unroll
        for(int ks=0; ks<4; ks++){
            unsigned afh[2][4], afl[2][4];
            #pragma unroll
            for(int mt=0; mt<2; mt++){
                unsigned ra = abase + (unsigned)(wc*32 + mt*16 + (lane&15))*144
                            + ((lane>>4)<<4) + ks*32;
                ldsm_x4(afh[mt], ra);
                ldsm_x4(afl[mt], ra + CV_TB);
            }
            #pragma unroll
            for(int ng=0; ng<4; ng++){
                unsigned bfh[4], bfl[4];
                unsigned rb = bbase + (unsigned)(wt*64 + ng*16 + ((lane>>4)<<3) + (lane&7))*144
                            + (((lane>>3)&1)<<4) + ks*32;
                ldsm_x4(bfh, rb);
                ldsm_x4(bfl, rb + CV_TB);
                #pragma unroll
                for(int mt=0; mt<2; mt++){
                    mma_bf16(acc[mt][ng*2  ], afh[mt], &bfh[0]);
                    mma_bf16(acc[mt][ng*2  ], afh[mt], &bfl[0]);
                    mma_bf16(acc[mt][ng*2  ], afl[mt], &bfh[0]);
                    mma_bf16(acc[mt][ng*2+1], afh[mt], &bfh[2]);
                    mma_bf16(acc[mt][ng*2+1], afh[mt], &bfl[2]);
                    mma_bf16(acc[mt][ng*2+1], afl[mt], &bfh[2]);
                }
            }
        }
        __syncthreads();
        if(ch+2<NCH) cov_issue(sb, buf, kbase + (ch+2)*64, i0, j0, diag, tid, xh, xl);
    }

    float* cp = g_covp + ((size_t)sl*Bb + b)*Cc*Cc;
    #pragma unroll
    for(int mt=0; mt<2; mt++){
        int r0 = i0 + wc*32 + mt*16 + (lane>>2);
        #pragma unroll
        for(int nt=0; nt<8; nt++){
            int co = j0 + wt*64 + nt*8 + (lane&3)*2;
            *(float2*)&cp[(size_t)r0*Cc + co]     = make_float2(acc[mt][nt][0], acc[mt][nt][1]);
            *(float2*)&cp[(size_t)(r0+8)*Cc + co] = make_float2(acc[mt][nt][2], acc[mt][nt][3]);
            if(!diag){
                cp[(size_t)co*Cc + r0]       = acc[mt][nt][0];
                cp[(size_t)(co+1)*Cc + r0]   = acc[mt][nt][1];
                cp[(size_t)co*Cc + r0+8]     = acc[mt][nt][2];
                cp[(size_t)(co+1)*Cc + r0+8] = acc[mt][nt][3];
            }
        }
    }
}

// =============================================================================
// K2b: row sums of G (4 slices). grid (Bb, 8): 32 rows per block, coalesced.
// =============================================================================
__global__ void __launch_bounds__(256) rowsum_kernel(){
    int b = blockIdx.x, rg = blockIdx.y;
    int tid = threadIdx.x, w = tid>>5, lane = tid&31;
    #pragma unroll
    for(int pass=0; pass<4; pass++){
        int r = rg*32 + pass*8 + w;
        float s = 0.f;
        #pragma unroll
        for(int sl=0; sl<4; sl++){
            const float* rp = g_covp + ((size_t)sl*Bb + b)*Cc*Cc + (size_t)r*Cc;
            #pragma unroll
            for(int j=0;j<8;j++) s += rp[j*32 + lane];
        }
        #pragma unroll
        for(int d=16; d>0; d>>=1) s += __shfl_xor_sync(0xffffffffu, s, d);
        if(lane==0) g_rs[b*Cc+r]=s;
    }
}

// =============================================================================
// K3: pcc rows + q/k projections, rebuilt. grid (8 cgroups, Bb); 256 thr.
// Weights loaded ONCE per block into smem, transposed [d][slot(e)] pad-65
// (slot = (e&7)*8 + e>>3 makes the inner read conflict-free). pcc rows for
// 32 c's staged in smem. Inner: 9 conflict-free LDS per 8 FMAs.
// =============================================================================
#define PQ_WS   (256*65)
#define PQ_PR   (32*260)
#define PQ_SMEM ((PQ_WS + PQ_PR + 256)*4)

__global__ void __launch_bounds__(256) pccqk_kernel(const float* __restrict__ qw, const float* __restrict__ qb,
                                                    const float* __restrict__ kw, const float* __restrict__ kb){
    extern __shared__ float sdyn[];
    float* ws   = sdyn;                 // [256 d][65]  permuted-e slots
    float* prow = ws + PQ_WS;           // [32 r][260]
    float* srs  = prow + PQ_PR;         // [256]
    __shared__ float sden, sSc;
    int tid = threadIdx.x;
    int cg = blockIdx.x, b = blockIdx.y;
    int c0 = cg*32;

    srs[tid] = g_rs[b*Cc + tid] * (1.0f/Cc);
    // weights, transposed + slot-permuted; coalesced global reads
    #pragma unroll
    for(int p=0;p<64;p++){
        int idx = p*256 + tid;
        int e = idx>>8, d = idx&255;
        float v = (e<32) ? qw[e*Cc+d] : kw[(e-32)*Cc+d];
        ws[d*65 + ((e&7)<<3) + (e>>3)] = v;
    }
    if(tid==0){
        float S=0.f;
        #pragma unroll 8
        for(int i=0;i<Cc;i++) S += srs[i];      // = Σrs/C
        sSc = S*(1.0f/Cc);                       // = S/C²
        float dn=0.f;
        #pragma unroll
        for(int i=0;i<32;i++) dn += g_varpart[b*32+i];
        sden = 1.0f/dn;
    }
    __syncthreads();

    // pcc rows with corrections: (G - rs_c/C - rs_d/C + S/C²) * sden
    float Sc = sSc, den = sden;
    #pragma unroll
    for(int p=0;p<8;p++){
        int idx = p*256 + tid;
        int r = idx>>6, d4 = (idx&63)*4;
        size_t off = ((size_t)(c0+r))*Cc + (size_t)b*Cc*Cc + d4;
        float4 v0 = *(const float4*)&g_covp[off];
        float4 v1 = *(const float4*)&g_covp[(size_t)SL + off];
        float4 v2 = *(const float4*)&g_covp[2*(size_t)SL + off];
        float4 v3 = *(const float4*)&g_covp[3*(size_t)SL + off];
        float rc = srs[c0+r] - Sc;
        prow[r*260 + d4+0] = (v0.x+v1.x+v2.x+v3.x - rc - srs[d4+0])*den;
        prow[r*260 + d4+1] = (v0.y+v1.y+v2.y+v3.y - rc - srs[d4+1])*den;
        prow[r*260 + d4+2] = (v0.z+v1.z+v2.z+v3.z - rc - srs[d4+2])*den;
        prow[r*260 + d4+3] = (v0.w+v1.w+v2.w+v3.w - rc - srs[d4+3])*den;
    }
    __syncthreads();

    // projection: thread (r = tid>>3, g = tid&7) -> e = g*8+j, j=0..7
    int r = tid>>3, g = tid&7;
    float acc[8];
    #pragma unroll
    for(int j=0;j<8;j++){
        int e = g*8 + j;
        acc[j] = (e<32) ? qb[e] : kb[e-32];
    }
    const float* pr = &prow[r*260];
    #pragma unroll 4
    for(int d=0; d<Cc; d++){
        float pv = pr[d];
        const float* wd = &ws[d*65 + g];
        #pragma unroll
        for(int j=0;j<8;j++) acc[j] += pv * wd[j*8];
    }
    int c = c0 + r;
    if(g<4){
        float* qp = &g_q[((size_t)b*Cc + c)*32 + g*8];
        *(float4*)&qp[0] = make_float4(acc[0],acc[1],acc[2],acc[3]);
        *(float4*)&qp[4] = make_float4(acc[4],acc[5],acc[6],acc[7]);
    }else{
        float* kp = &g_k[((size_t)b*Cc + c)*32 + (g-4)*8];
        *(float4*)&kp[0] = make_float4(acc[0],acc[1],acc[2],acc[3]);
        *(float4*)&kp[4] = make_float4(acc[4],acc[5],acc[6],acc[7]);
    }
}

// =============================================================================
// K4: scores + softmax, warp-per-query (EXACT R12 — known-good)
// =============================================================================
__global__ void __launch_bounds__(256) attn_kernel(float* __restrict__ out){
    int bg = blockIdx.x, b = blockIdx.y;
    int tid = threadIdx.x, w = tid>>5, lane = tid&31;
    __shared__ float ks[256][36];
    __shared__ float qs[32][36];
    const float* kp = g_k + (size_t)b*Cc*32;
    int c0 = bg*32;
    #pragma unroll
    for(int p=0;p<8;p++){
        int idx = tid + p*256;
        int d = idx>>3, e4 = (idx&7)*4;
        *(float4*)&ks[d][e4] = *(const float4*)&kp[d*32 + e4];
    }
    {
        int q = tid>>3, e4 = (tid&7)*4;
        *(float4*)&qs[q][e4] = *(const float4*)&g_q[((size_t)b*Cc + c0 + q)*32 + e4];
    }
    __syncthreads();
    float* ao = out + OUT_ELEMS + ((size_t)b*Cc + c0)*Cc;
    #pragma unroll
    for(int qi=0; qi<4; qi++){
        int q = w*4 + qi;
        float s[8];
        #pragma unroll
        for(int m=0;m<8;m++) s[m]=0.f;
        #pragma unroll
        for(int e4=0;e4<8;e4++){
            float4 qv = *(const float4*)&qs[q][e4*4];
            #pragma unroll
            for(int m=0;m<8;m++){
                float4 kv = *(const float4*)&ks[m*32+lane][e4*4];
                s[m] += qv.x*kv.x + qv.y*kv.y + qv.z*kv.z + qv.w*kv.w;
            }
        }
        float mx = s[0]*(1.0f/16.0f);
        #pragma unroll
        for(int m=0;m<8;m++){ s[m] *= (1.0f/16.0f); mx = fmaxf(mx, s[m]); }
        #pragma unroll
        for(int d=16; d>0; d>>=1) mx = fmaxf(mx, __shfl_xor_sync(0xffffffffu, mx, d));
        float ev[8], sm=0.f;
        #pragma unroll
        for(int m=0;m<8;m++){ ev[m] = expf(s[m]-mx); sm += ev[m]; }
        #pragma unroll
        for(int d=16; d>0; d>>=1) sm += __shfl_xor_sync(0xffffffffu, sm, d);
        float inv = 1.0f/sm;
        #pragma unroll
        for(int m=0;m<8;m++){
            float a = ev[m]*inv;
            size_t idx = ((size_t)b*Cc + c0 + q)*Cc + m*32 + lane;
            ao[(size_t)q*Cc + m*32 + lane] = a;
            __nv_bfloat16 h = __float2bfloat16(a);
            g_attn_h[idx] = h;
            g_attn_l[idx] = __float2bfloat16(a - __bfloat162float(h));
        }
    }
}

// =============================================================================
// K5: out = attn @ x via mma.sync bf16x3 (EXACT R12 — known-good)
// =============================================================================
#define OG_AH 0
#define OG_AL 18432
#define OG_BH 36864
#define OG_BL 54272
#define OG_ST 71680
#define OG_SMEM (71680 + 33792)

__global__ void __launch_bounds__(256) out_gemm_mma(const float* __restrict__ x,
                                                    float* __restrict__ out){
    extern __shared__ char sm[];
    unsigned sb = smem_u32(sm);
    int tid = threadIdx.x, w = tid>>5, lane = tid&31;
    int t0 = blockIdx.x*128, c0 = blockIdx.y*128, b = blockIdx.z;
    const float* xb = x + (size_t)b*Cc*Tt;
    const __nv_bfloat16* ah = g_attn_h + (size_t)b*Cc*Cc;
    const __nv_bfloat16* al = g_attn_l + (size_t)b*Cc*Cc;
    int wc = w&3, wt = w>>2;

    float acc[2][8][4];
    #pragma unroll
    for(int i=0;i<2;i++)
        #pragma unroll
        for(int j=0;j<8;j++)
            #pragma unroll
            for(int r=0;r<4;r++) acc[i][j][r]=0.f;

    #pragma unroll 1
    for(int ch=0; ch<4; ++ch){
        int d0 = ch*64;
        if(ch>0) __syncthreads();

        #pragma unroll
        for(int p=0;p<8;p++){
            int lin = p*256 + tid;
            int arr = lin>>10, r = (lin>>3)&127, u = lin&7;
            const __nv_bfloat16* src = (arr ? al : ah) + (size_t)(c0+r)*Cc + d0 + u*8;
            cpasync16(sb + (arr ? OG_AL : OG_AH) + r*144 + u*16, src);
        }
        #pragma unroll
        for(int p=0;p<8;p++){
            int lin = p*256 + tid;
            int r = lin>>5, u = lin&31;
            cpasync16(sb + OG_ST + r*528 + u*16, &xb[(size_t)(d0+r)*Tt + t0 + u*4]);
        }
        asm volatile("cp.async.commit_group;" ::: "memory");
        asm volatile("cp.async.wait_group 0;" ::: "memory");
        __syncthreads();

        {
            int d = tid>>2, tg = tid&3;
            const float* sr = (const float*)(sm + OG_ST) + d*132 + tg*32;
            #pragma unroll
            for(int j=0;j<8;j++){
                float4 v = *(const float4*)&sr[j*4];
                float vv[4] = {v.x, v.y, v.z, v.w};
                unsigned hb[4], lb[4];
                #pragma unroll
                for(int i=0;i<4;i++){
                    __nv_bfloat16 h = __float2bfloat16(vv[i]);
                    __nv_bfloat16 l = __float2bfloat16(vv[i] - __bfloat162float(h));
                    hb[i] = __bfloat16_as_ushort(h);
                    lb[i] = __bfloat16_as_ushort(l);
                }
                int t = tg*32 + j*4;
                *(uint2*)(sm + OG_BH + d*272 + t*2) = make_uint2(hb[0]|(hb[1]<<16), hb[2]|(hb[3]<<16));
                *(uint2*)(sm + OG_BL + d*272 + t*2) = make_uint2(lb[0]|(lb[1]<<16), lb[2]|(lb[3]<<16));
            }
        }
        __syncthreads();

        #pragma unroll
        for(int ks=0; ks<4; ks++){
            int k0 = ks*16;
            unsigned afh[2][4], afl[2][4];
            #pragma unroll
            for(int mt=0; mt<2; mt++){
                unsigned ra = sb + OG_AH + (unsigned)(wc*32 + mt*16 + (lane&15))*144
                            + k0*2 + ((lane>>4)<<4);
                ldsm_x4(afh[mt], ra);
                ldsm_x4(afl[mt], ra + (OG_AL - OG_AH));
            }
            unsigned bfh[4][4], bfl[4][4];
            int kk = k0 + (lane&7) + (((lane>>3)&1)<<3);
            #pragma unroll
            for(int ng=0; ng<4; ng++){
                int tt = wt*64 + ng*16 + (((lane>>4)&1)<<3);
                unsigned rb = sb + OG_BH + (unsigned)kk*272 + tt*2;
                ldsm_x4_t(bfh[ng], rb);
                ldsm_x4_t(bfl[ng], rb + (OG_BL - OG_BH));
            }
            #pragma unroll
            for(int mt=0; mt<2; mt++){
                #pragma unroll
                for(int ng=0; ng<4; ng++){
                    mma_bf16(acc[mt][ng*2  ], afh[mt], &bfh[ng][0]);
                    mma_bf16(acc[mt][ng*2  ], afh[mt], &bfl[ng][0]);
                    mma_bf16(acc[mt][ng*2  ], afl[mt], &bfh[ng][0]);
                    mma_bf16(acc[mt][ng*2+1], afh[mt], &bfh[ng][2]);
                    mma_bf16(acc[mt][ng*2+1], afh[mt], &bfl[ng][2]);
                    mma_bf16(acc[mt][ng*2+1], afl[mt], &bfh[ng][2]);
                }
            }
        }
    }

    float* ob = out + (size_t)b*Cc*Tt;
    #pragma unroll
    for(int mt=0; mt<2; mt++){
        int r0 = c0 + wc*32 + mt*16 + (lane>>2);
        #pragma unroll
        for(int nt=0; nt<8; nt++){
            int t = t0 + wt*64 + nt*8 + (lane&3)*2;
            *(float2*)&ob[(size_t)r0*Tt + t]     = make_float2(acc[mt][nt][0], acc[mt][nt][1]);
            *(float2*)&ob[(size_t)(r0+8)*Tt + t] = make_float2(acc[mt][nt][2], acc[mt][nt][3]);
        }
    }
}

// =============================================================================
extern "C" void kernel_launch(void* const* d_in, const int* in_sizes, int n_in,
                              void* d_out, int out_size){
    const float* x  = (const float*)d_in[0];
    const float* qw = (const float*)d_in[1];
    const float* qb = (const float*)d_in[2];
    const float* kw = (const float*)d_in[3];
    const float* kb = (const float*)d_in[4];
    float* out = (float*)d_out;

    cudaFuncSetAttribute(out_gemm_mma, cudaFuncAttributeMaxDynamicSharedMemorySize, OG_SMEM);
    cudaFuncSetAttribute(cov_mma, cudaFuncAttributeMaxDynamicSharedMemorySize, CV_SMEM);
    cudaFuncSetAttribute(pccqk_kernel, cudaFuncAttributeMaxDynamicSharedMemorySize, PQ_SMEM);

    stats_kernel <<<dim3(Tt/256, Bb), 256>>>(x);
    cov_mma      <<<dim3(3, Bb, KSPLIT), 256, CV_SMEM>>>();
    rowsum_kernel<<<dim3(Bb, 8), 256>>>();
    pccqk_kernel <<<dim3(8, Bb), 256, PQ_SMEM>>>(qw, qb, kw, kb);
    attn_kernel  <<<dim3(Cc/32, Bb), 256>>>(out);
    out_gemm_mma <<<dim3(Tt/128, Cc/128, Bb), 256, OG_SMEM>>>(x, out);
}

// round 15
// speedup vs baseline: 2.7614x; 1.2375x over previous
#include <cuda_runtime.h>
#include <cuda_bf16.h>
#include <math.h>

#define Bb 16
#define Cc 256
#define Tt 8192
#define KSPLIT 4
#define SL (Bb*Cc*Cc)
#define OUT_ELEMS ((size_t)Bb*Cc*Tt)

typedef unsigned long long u64;

// ---------------- scratch (static device globals; no allocation) -------------
__device__ float g_varpart[Bb*32];
__device__ float g_covp[(size_t)KSPLIT*SL];
__device__ float g_rs[Bb*Cc];
__device__ float g_q[Bb*Cc*32];
__device__ float g_k[Bb*Cc*32];
__device__ __nv_bfloat16 g_xh[(size_t)Bb*Cc*Tt];      // x hi bf16
__device__ __nv_bfloat16 g_xl[(size_t)Bb*Cc*Tt];      // x lo bf16
__device__ __nv_bfloat16 g_attn_h[(size_t)Bb*Cc*Cc];  // attn hi [b][c][d]
__device__ __nv_bfloat16 g_attn_l[(size_t)Bb*Cc*Cc];  // attn lo [b][c][d]

// ---------------- mma.sync helpers (sm_80+ ISA) ------------------------------
__device__ __forceinline__ unsigned smem_u32(const void* p){
    unsigned a; asm("{ .reg .u64 t; cvta.to.shared.u64 t, %1; cvt.u32.u64 %0, t; }" : "=r"(a) : "l"(p)); return a;
}
__device__ __forceinline__ void cpasync16(unsigned dst, const void* src){
    asm volatile("cp.async.cg.shared.global [%0], [%1], 16;" :: "r"(dst), "l"(src));
}
__device__ __forceinline__ void ldsm_x4(unsigned* r, unsigned addr){
    asm volatile("ldmatrix.sync.aligned.m8n8.x4.shared.b16 {%0,%1,%2,%3}, [%4];"
        : "=r"(r[0]), "=r"(r[1]), "=r"(r[2]), "=r"(r[3]) : "r"(addr));
}
__device__ __forceinline__ void ldsm_x4_t(unsigned* r, unsigned addr){
    asm volatile("ldmatrix.sync.aligned.m8n8.x4.trans.shared.b16 {%0,%1,%2,%3}, [%4];"
        : "=r"(r[0]), "=r"(r[1]), "=r"(r[2]), "=r"(r[3]) : "r"(addr));
}
__device__ __forceinline__ void mma_bf16(float* d, const unsigned* a, const unsigned* b){
    asm volatile("mma.sync.aligned.m16n8k16.row.col.f32.bf16.bf16.f32 "
        "{%0,%1,%2,%3}, {%4,%5,%6,%7}, {%8,%9}, {%0,%1,%2,%3};"
        : "+f"(d[0]), "+f"(d[1]), "+f"(d[2]), "+f"(d[3])
        : "r"(a[0]), "r"(a[1]), "r"(a[2]), "r"(a[3]), "r"(b[0]), "r"(b[1]));
}

// =============================================================================
// K1: per-(b,t) variance partials (ddof=1) + write x as bf16 hi/lo (R12)
// =============================================================================
__global__ void __launch_bounds__(256) stats_kernel(const float* __restrict__ x){
    int b = blockIdx.y;
    int t = blockIdx.x*256 + threadIdx.x;
    size_t base = (size_t)b*Cc*Tt + t;
    const float* xp = x + base;
    __nv_bfloat16* xh = g_xh + base;
    __nv_bfloat16* xl = g_xl + base;
    float s0=0.f,s1=0.f,q0=0.f,q1=0.f;
    #pragma unroll 4
    for(int c=0;c<Cc;c+=2){
        float v0 = xp[(size_t)c*Tt];
        float v1 = xp[(size_t)(c+1)*Tt];
        s0+=v0; q0+=v0*v0;
        s1+=v1; q1+=v1*v1;
        __nv_bfloat16 h0 = __float2bfloat16(v0);
        __nv_bfloat16 h1 = __float2bfloat16(v1);
        xh[(size_t)c*Tt]     = h0;
        xh[(size_t)(c+1)*Tt] = h1;
        xl[(size_t)c*Tt]     = __float2bfloat16(v0 - __bfloat162float(h0));
        xl[(size_t)(c+1)*Tt] = __float2bfloat16(v1 - __bfloat162float(h1));
    }
    float s=s0+s1, q=q0+q1;
    float mean = s*(1.0f/Cc);
    float var = (q - s*mean)*(1.0f/(Cc-1));
    __shared__ float red[256];
    int tid = threadIdx.x;
    red[tid]=var; __syncthreads();
    for(int w=128;w>0;w>>=1){ if(tid<w) red[tid]+=red[tid+w]; __syncthreads(); }
    if(tid==0) g_varpart[b*32+blockIdx.x]=red[0];
}

// =============================================================================
// K2: G = X X^T partials via mma.sync bf16x3 (EXACT R12 — known-good)
// =============================================================================
__constant__ int t2_i[3]={0,0,1};
__constant__ int t2_j[3]={0,1,1};

#define CV_TB   18432
#define CV_BUF  73728
#define CV_SMEM (2*CV_BUF)

__device__ __forceinline__ void cov_issue(unsigned sb, int buf, int kg, int i0, int j0,
                                          bool diag, int tid,
                                          const __nv_bfloat16* xh, const __nv_bfloat16* xl){
    #pragma unroll
    for(int p=0;p<8;p++){
        int lin = p*256 + tid;
        int arr = lin>>10, r = (lin>>3)&127, u = lin&7;
        const __nv_bfloat16* s = (arr ? xl : xh) + (size_t)(i0+r)*Tt + kg + u*8;
        cpasync16(sb + buf*CV_BUF + arr*CV_TB + r*144 + u*16, s);
    }
    if(!diag){
        #pragma unroll
        for(int p=0;p<8;p++){
            int lin = p*256 + tid;
            int arr = lin>>10, r = (lin>>3)&127, u = lin&7;
            const __nv_bfloat16* s = (arr ? xl : xh) + (size_t)(j0+r)*Tt + kg + u*8;
            cpasync16(sb + buf*CV_BUF + 2*CV_TB + arr*CV_TB + r*144 + u*16, s);
        }
    }
    asm volatile("cp.async.commit_group;" ::: "memory");
}

__global__ void __launch_bounds__(256) cov_mma(){
    extern __shared__ char sm[];
    unsigned sb = smem_u32(sm);
    int tid = threadIdx.x, w = tid>>5, lane = tid&31;
    int tile = blockIdx.x, b = blockIdx.y, sl = blockIdx.z;
    int i0 = t2_i[tile]*128, j0 = t2_j[tile]*128;
    bool diag = (i0==j0);
    int wc = w&3, wt = w>>2;
    const __nv_bfloat16* xh = g_xh + (size_t)b*Cc*Tt;
    const __nv_bfloat16* xl = g_xl + (size_t)b*Cc*Tt;
    int kbase = sl*(Tt/KSPLIT);
    const int NCH = (Tt/KSPLIT)/64;

    float acc[2][8][4];
    #pragma unroll
    for(int i=0;i<2;i++)
        #pragma unroll
        for(int j=0;j<8;j++)
            #pragma unroll
            for(int r=0;r<4;r++) acc[i][j][r]=0.f;

    cov_issue(sb, 0, kbase,    i0, j0, diag, tid, xh, xl);
    cov_issue(sb, 1, kbase+64, i0, j0, diag, tid, xh, xl);

    #pragma unroll 1
    for(int ch=0; ch<NCH; ++ch){
        int buf = ch&1;
        if(ch==NCH-1) asm volatile("cp.async.wait_group 0;" ::: "memory");
        else          asm volatile("cp.async.wait_group 1;" ::: "memory");
        __syncthreads();
        unsigned abase = sb + buf*CV_BUF;
        unsigned bbase = abase + (diag ? 0u : 2u*CV_TB);
        #pragma unroll
        for(int ks=0; ks<4; ks++){
            unsigned afh[2][4], afl[2][4];
            #pragma unroll
            for(int mt=0; mt<2; mt++){
                unsigned ra = abase + (unsigned)(wc*32 + mt*16 + (lane&15))*144
                            + ((lane>>4)<<4) + ks*32;
                ldsm_x4(afh[mt], ra);
                ldsm_x4(afl[mt], ra + CV_TB);
            }
            #pragma unroll
            for(int ng=0; ng<4; ng++){
                unsigned bfh[4], bfl[4];
                unsigned rb = bbase + (unsigned)(wt*64 + ng*16 + ((lane>>4)<<3) + (lane&7))*144
                            + (((lane>>3)&1)<<4) + ks*32;
                ldsm_x4(bfh, rb);
                ldsm_x4(bfl, rb + CV_TB);
                #pragma unroll
                for(int mt=0; mt<2; mt++){
                    mma_bf16(acc[mt][ng*2  ], afh[mt], &bfh[0]);
                    mma_bf16(acc[mt][ng*2  ], afh[mt], &bfl[0]);
                    mma_bf16(acc[mt][ng*2  ], afl[mt], &bfh[0]);
                    mma_bf16(acc[mt][ng*2+1], afh[mt], &bfh[2]);
                    mma_bf16(acc[mt][ng*2+1], afh[mt], &bfl[2]);
                    mma_bf16(acc[mt][ng*2+1], afl[mt], &bfh[2]);
                }
            }
        }
        __syncthreads();
        if(ch+2<NCH) cov_issue(sb, buf, kbase + (ch+2)*64, i0, j0, diag, tid, xh, xl);
    }

    float* cp = g_covp + ((size_t)sl*Bb + b)*Cc*Cc;
    #pragma unroll
    for(int mt=0; mt<2; mt++){
        int r0 = i0 + wc*32 + mt*16 + (lane>>2);
        #pragma unroll
        for(int nt=0; nt<8; nt++){
            int co = j0 + wt*64 + nt*8 + (lane&3)*2;
            *(float2*)&cp[(size_t)r0*Cc + co]     = make_float2(acc[mt][nt][0], acc[mt][nt][1]);
            *(float2*)&cp[(size_t)(r0+8)*Cc + co] = make_float2(acc[mt][nt][2], acc[mt][nt][3]);
            if(!diag){
                cp[(size_t)co*Cc + r0]       = acc[mt][nt][0];
                cp[(size_t)(co+1)*Cc + r0]   = acc[mt][nt][1];
                cp[(size_t)co*Cc + r0+8]     = acc[mt][nt][2];
                cp[(size_t)(co+1)*Cc + r0+8] = acc[mt][nt][3];
            }
        }
    }
}

// =============================================================================
// K2b: row sums of G (4 slices). grid (Bb, 8) (R13 — known-good)
// =============================================================================
__global__ void __launch_bounds__(256) rowsum_kernel(){
    int b = blockIdx.x, rg = blockIdx.y;
    int tid = threadIdx.x, w = tid>>5, lane = tid&31;
    #pragma unroll
    for(int pass=0; pass<4; pass++){
        int r = rg*32 + pass*8 + w;
        float s = 0.f;
        #pragma unroll
        for(int sl=0; sl<4; sl++){
            const float* rp = g_covp + ((size_t)sl*Bb + b)*Cc*Cc + (size_t)r*Cc;
            #pragma unroll
            for(int j=0;j<8;j++) s += rp[j*32 + lane];
        }
        #pragma unroll
        for(int d=16; d>0; d>>=1) s += __shfl_xor_sync(0xffffffffu, s, d);
        if(lane==0) g_rs[b*Cc+r]=s;
    }
}

// =============================================================================
// K3: pcc rows + q/k projections (EXACT R13 — known-good, 24us)
// =============================================================================
#define PQ_WS   (256*65)
#define PQ_PR   (32*260)
#define PQ_SMEM ((PQ_WS + PQ_PR + 256)*4)

__global__ void __launch_bounds__(256) pccqk_kernel(const float* __restrict__ qw, const float* __restrict__ qb,
                                                    const float* __restrict__ kw, const float* __restrict__ kb){
    extern __shared__ float sdyn[];
    float* ws   = sdyn;
    float* prow = ws + PQ_WS;
    float* srs  = prow + PQ_PR;
    __shared__ float sden, sSc;
    int tid = threadIdx.x;
    int cg = blockIdx.x, b = blockIdx.y;
    int c0 = cg*32;

    srs[tid] = g_rs[b*Cc + tid] * (1.0f/Cc);
    #pragma unroll
    for(int p=0;p<64;p++){
        int idx = p*256 + tid;
        int e = idx>>8, d = idx&255;
        float v = (e<32) ? qw[e*Cc+d] : kw[(e-32)*Cc+d];
        ws[d*65 + ((e&7)<<3) + (e>>3)] = v;
    }
    if(tid==0){
        float S=0.f;
        #pragma unroll 8
        for(int i=0;i<Cc;i++) S += srs[i];
        sSc = S*(1.0f/Cc);
        float dn=0.f;
        #pragma unroll
        for(int i=0;i<32;i++) dn += g_varpart[b*32+i];
        sden = 1.0f/dn;
    }
    __syncthreads();

    float Sc = sSc, den = sden;
    #pragma unroll
    for(int p=0;p<8;p++){
        int idx = p*256 + tid;
        int r = idx>>6, d4 = (idx&63)*4;
        size_t off = ((size_t)(c0+r))*Cc + (size_t)b*Cc*Cc + d4;
        float4 v0 = *(const float4*)&g_covp[off];
        float4 v1 = *(const float4*)&g_covp[(size_t)SL + off];
        float4 v2 = *(const float4*)&g_covp[2*(size_t)SL + off];
        float4 v3 = *(const float4*)&g_covp[3*(size_t)SL + off];
        float rc = srs[c0+r] - Sc;
        prow[r*260 + d4+0] = (v0.x+v1.x+v2.x+v3.x - rc - srs[d4+0])*den;
        prow[r*260 + d4+1] = (v0.y+v1.y+v2.y+v3.y - rc - srs[d4+1])*den;
        prow[r*260 + d4+2] = (v0.z+v1.z+v2.z+v3.z - rc - srs[d4+2])*den;
        prow[r*260 + d4+3] = (v0.w+v1.w+v2.w+v3.w - rc - srs[d4+3])*den;
    }
    __syncthreads();

    int r = tid>>3, g = tid&7;
    float acc[8];
    #pragma unroll
    for(int j=0;j<8;j++){
        int e = g*8 + j;
        acc[j] = (e<32) ? qb[e] : kb[e-32];
    }
    const float* pr = &prow[r*260];
    #pragma unroll 4
    for(int d=0; d<Cc; d++){
        float pv = pr[d];
        const float* wd = &ws[d*65 + g];
        #pragma unroll
        for(int j=0;j<8;j++) acc[j] += pv * wd[j*8];
    }
    int c = c0 + r;
    if(g<4){
        float* qp = &g_q[((size_t)b*Cc + c)*32 + g*8];
        *(float4*)&qp[0] = make_float4(acc[0],acc[1],acc[2],acc[3]);
        *(float4*)&qp[4] = make_float4(acc[4],acc[5],acc[6],acc[7]);
    }else{
        float* kp = &g_k[((size_t)b*Cc + c)*32 + (g-4)*8];
        *(float4*)&kp[0] = make_float4(acc[0],acc[1],acc[2],acc[3]);
        *(float4*)&kp[4] = make_float4(acc[4],acc[5],acc[6],acc[7]);
    }
}

// =============================================================================
// K4: scores + softmax, warp-per-query (EXACT R13 — known-good)
// =============================================================================
__global__ void __launch_bounds__(256) attn_kernel(float* __restrict__ out){
    int bg = blockIdx.x, b = blockIdx.y;
    int tid = threadIdx.x, w = tid>>5, lane = tid&31;
    __shared__ float ks[256][36];
    __shared__ float qs[32][36];
    const float* kp = g_k + (size_t)b*Cc*32;
    int c0 = bg*32;
    #pragma unroll
    for(int p=0;p<8;p++){
        int idx = tid + p*256;
        int d = idx>>3, e4 = (idx&7)*4;
        *(float4*)&ks[d][e4] = *(const float4*)&kp[d*32 + e4];
    }
    {
        int q = tid>>3, e4 = (tid&7)*4;
        *(float4*)&qs[q][e4] = *(const float4*)&g_q[((size_t)b*Cc + c0 + q)*32 + e4];
    }
    __syncthreads();
    float* ao = out + OUT_ELEMS + ((size_t)b*Cc + c0)*Cc;
    #pragma unroll
    for(int qi=0; qi<4; qi++){
        int q = w*4 + qi;
        float s[8];
        #pragma unroll
        for(int m=0;m<8;m++) s[m]=0.f;
        #pragma unroll
        for(int e4=0;e4<8;e4++){
            float4 qv = *(const float4*)&qs[q][e4*4];
            #pragma unroll
            for(int m=0;m<8;m++){
                float4 kv = *(const float4*)&ks[m*32+lane][e4*4];
                s[m] += qv.x*kv.x + qv.y*kv.y + qv.z*kv.z + qv.w*kv.w;
            }
        }
        float mx = s[0]*(1.0f/16.0f);
        #pragma unroll
        for(int m=0;m<8;m++){ s[m] *= (1.0f/16.0f); mx = fmaxf(mx, s[m]); }
        #pragma unroll
        for(int d=16; d>0; d>>=1) mx = fmaxf(mx, __shfl_xor_sync(0xffffffffu, mx, d));
        float ev[8], sm=0.f;
        #pragma unroll
        for(int m=0;m<8;m++){ ev[m] = expf(s[m]-mx); sm += ev[m]; }
        #pragma unroll
        for(int d=16; d>0; d>>=1) sm += __shfl_xor_sync(0xffffffffu, sm, d);
        float inv = 1.0f/sm;
        #pragma unroll
        for(int m=0;m<8;m++){
            float a = ev[m]*inv;
            size_t idx = ((size_t)b*Cc + c0 + q)*Cc + m*32 + lane;
            ao[(size_t)q*Cc + m*32 + lane] = a;
            __nv_bfloat16 h = __float2bfloat16(a);
            g_attn_h[idx] = h;
            g_attn_l[idx] = __float2bfloat16(a - __bfloat162float(h));
        }
    }
}

// =============================================================================
// K5: out = attn @ x, c-supertile (R14 structure, B-tile mapping FIXED:
// 16 uint4 per 272B row, r=la>>4, u=la&15). x read once as bf16 hi/lo.
// =============================================================================
#define O2_AL   36864
#define O2_B    73728
#define O2_BL   17408
#define O2_BUF  108544
#define O2_SMEM (2*O2_BUF)

__device__ __forceinline__ void og2_issue(unsigned sb, int buf, int d0, int t0,
                                          int tid,
                                          const __nv_bfloat16* ah, const __nv_bfloat16* al,
                                          const __nv_bfloat16* xh, const __nv_bfloat16* xl){
    unsigned dst = sb + buf*O2_BUF;
    #pragma unroll
    for(int p=0;p<16;p++){                  // A: 256 rows x 8 uint4 x2 arrays
        int lin = p*256 + tid;
        int arr = lin>>11, r = (lin>>3)&255, u = lin&7;
        const __nv_bfloat16* s = (arr ? al : ah) + (size_t)r*Cc + d0 + u*8;
        cpasync16(dst + arr*O2_AL + r*144 + u*16, s);
    }
    #pragma unroll
    for(int p=0;p<8;p++){                   // B: 64 rows x 16 uint4 x2 arrays
        int lin = p*256 + tid;
        int arr = lin>>10, la = lin&1023;
        int r = la>>4, u = la&15;
        const __nv_bfloat16* s = (arr ? xl : xh) + (size_t)(d0+r)*Tt + t0 + u*8;
        cpasync16(dst + O2_B + arr*O2_BL + r*272 + u*16, s);
    }
    asm volatile("cp.async.commit_group;" ::: "memory");
}

__global__ void __launch_bounds__(256) out_gemm_mma(float* __restrict__ out){
    extern __shared__ char sm[];
    unsigned sb = smem_u32(sm);
    int tid = threadIdx.x, w = tid>>5, lane = tid&31;
    int t0 = blockIdx.x*128, b = blockIdx.y;
    const __nv_bfloat16* xh = g_xh + (size_t)b*Cc*Tt;
    const __nv_bfloat16* xl = g_xl + (size_t)b*Cc*Tt;
    const __nv_bfloat16* ah = g_attn_h + (size_t)b*Cc*Cc;
    const __nv_bfloat16* al = g_attn_l + (size_t)b*Cc*Cc;
    int wc = w&3, wt = w>>2;                // warp: 64 c x 64 t

    float acc[4][8][4];
    #pragma unroll
    for(int i=0;i<4;i++)
        #pragma unroll
        for(int j=0;j<8;j++)
            #pragma unroll
            for(int r=0;r<4;r++) acc[i][j][r]=0.f;

    og2_issue(sb, 0, 0,  t0, tid, ah, al, xh, xl);
    og2_issue(sb, 1, 64, t0, tid, ah, al, xh, xl);

    #pragma unroll 1
    for(int ch=0; ch<4; ++ch){
        int buf = ch&1;
        if(ch==3) asm volatile("cp.async.wait_group 0;" ::: "memory");
        else      asm volatile("cp.async.wait_group 1;" ::: "memory");
        __syncthreads();
        unsigned abase = sb + buf*O2_BUF;
        unsigned bbase = abase + O2_B;
        #pragma unroll
        for(int ks=0; ks<4; ks++){
            int k0 = ks*16;
            unsigned bfh[4][4], bfl[4][4];
            int kk = k0 + (lane&7) + (((lane>>3)&1)<<3);
            #pragma unroll
            for(int ng=0; ng<4; ng++){
                int tt = wt*64 + ng*16 + (((lane>>4)&1)<<3);
                unsigned rb = bbase + (unsigned)kk*272 + tt*2;
                ldsm_x4_t(bfh[ng], rb);
                ldsm_x4_t(bfl[ng], rb + O2_BL);
            }
            #pragma unroll
            for(int mt=0; mt<4; mt++){
                unsigned afh[4], afl[4];
                unsigned ra = abase + (unsigned)(wc*64 + mt*16 + (lane&15))*144
                            + k0*2 + ((lane>>4)<<4);
                ldsm_x4(afh, ra);
                ldsm_x4(afl, ra + O2_AL);
                #pragma unroll
                for(int ng=0; ng<4; ng++){
                    mma_bf16(acc[mt][ng*2  ], afh, &bfh[ng][0]);
                    mma_bf16(acc[mt][ng*2  ], afh, &bfl[ng][0]);
                    mma_bf16(acc[mt][ng*2  ], afl, &bfh[ng][0]);
                    mma_bf16(acc[mt][ng*2+1], afh, &bfh[ng][2]);
                    mma_bf16(acc[mt][ng*2+1], afh, &bfl[ng][2]);
                    mma_bf16(acc[mt][ng*2+1], afl, &bfh[ng][2]);
                }
            }
        }
        __syncthreads();
        if(ch+2<4) og2_issue(sb, buf, (ch+2)*64, t0, tid, ah, al, xh, xl);
    }

    float* ob = out + (size_t)b*Cc*Tt;
    #pragma unroll
    for(int mt=0; mt<4; mt++){
        int r0 = wc*64 + mt*16 + (lane>>2);
        #pragma unroll
        for(int nt=0; nt<8; nt++){
            int t = t0 + wt*64 + nt*8 + (lane&3)*2;
            *(float2*)&ob[(size_t)r0*Tt + t]     = make_float2(acc[mt][nt][0], acc[mt][nt][1]);
            *(float2*)&ob[(size_t)(r0+8)*Tt + t] = make_float2(acc[mt][nt][2], acc[mt][nt][3]);
        }
    }
}

// =============================================================================
extern "C" void kernel_launch(void* const* d_in, const int* in_sizes, int n_in,
                              void* d_out, int out_size){
    const float* x  = (const float*)d_in[0];
    const float* qw = (const float*)d_in[1];
    const float* qb = (const float*)d_in[2];
    const float* kw = (const float*)d_in[3];
    const float* kb = (const float*)d_in[4];
    float* out = (float*)d_out;

    cudaFuncSetAttribute(out_gemm_mma, cudaFuncAttributeMaxDynamicSharedMemorySize, O2_SMEM);
    cudaFuncSetAttribute(cov_mma, cudaFuncAttributeMaxDynamicSharedMemorySize, CV_SMEM);
    cudaFuncSetAttribute(pccqk_kernel, cudaFuncAttributeMaxDynamicSharedMemorySize, PQ_SMEM);

    stats_kernel <<<dim3(Tt/256, Bb), 256>>>(x);
    cov_mma      <<<dim3(3, Bb, KSPLIT), 256, CV_SMEM>>>();
    rowsum_kernel<<<dim3(Bb, 8), 256>>>();
    pccqk_kernel <<<dim3(8, Bb), 256, PQ_SMEM>>>(qw, qb, kw, kb);
    attn_kernel  <<<dim3(Cc/32, Bb), 256>>>(out);
    out_gemm_mma <<<dim3(Tt/128, Bb), 256, O2_SMEM>>>(out);
}

// round 16
// speedup vs baseline: 2.8081x; 1.0169x over previous
#include <cuda_runtime.h>
#include <cuda_bf16.h>
#include <math.h>

#define Bb 16
#define Cc 256
#define Tt 8192
#define KSPLIT 2
#define SL (Bb*Cc*Cc)
#define OUT_ELEMS ((size_t)Bb*Cc*Tt)

typedef unsigned long long u64;

// ---------------- scratch (static device globals; no allocation) -------------
__device__ float g_covp[(size_t)KSPLIT*SL];
__device__ float g_rs[Bb*Cc];
__device__ float g_diag[Bb*Cc];
__device__ float g_q[Bb*Cc*32];
__device__ float g_k[Bb*Cc*32];
__device__ __nv_bfloat16 g_xh[(size_t)Bb*Cc*Tt];      // x hi bf16
__device__ __nv_bfloat16 g_xl[(size_t)Bb*Cc*Tt];      // x lo bf16
__device__ __nv_bfloat16 g_attn_h[(size_t)Bb*Cc*Cc];  // attn hi [b][c][d]
__device__ __nv_bfloat16 g_attn_l[(size_t)Bb*Cc*Cc];  // attn lo [b][c][d]

// ---------------- mma.sync helpers (sm_80+ ISA) ------------------------------
__device__ __forceinline__ unsigned smem_u32(const void* p){
    unsigned a; asm("{ .reg .u64 t; cvta.to.shared.u64 t, %1; cvt.u32.u64 %0, t; }" : "=r"(a) : "l"(p)); return a;
}
__device__ __forceinline__ void cpasync16(unsigned dst, const void* src){
    asm volatile("cp.async.cg.shared.global [%0], [%1], 16;" :: "r"(dst), "l"(src));
}
__device__ __forceinline__ void ldsm_x4(unsigned* r, unsigned addr){
    asm volatile("ldmatrix.sync.aligned.m8n8.x4.shared.b16 {%0,%1,%2,%3}, [%4];"
        : "=r"(r[0]), "=r"(r[1]), "=r"(r[2]), "=r"(r[3]) : "r"(addr));
}
__device__ __forceinline__ void ldsm_x4_t(unsigned* r, unsigned addr){
    asm volatile("ldmatrix.sync.aligned.m8n8.x4.trans.shared.b16 {%0,%1,%2,%3}, [%4];"
        : "=r"(r[0]), "=r"(r[1]), "=r"(r[2]), "=r"(r[3]) : "r"(addr));
}
__device__ __forceinline__ void mma_bf16(float* d, const unsigned* a, const unsigned* b){
    asm volatile("mma.sync.aligned.m16n8k16.row.col.f32.bf16.bf16.f32 "
        "{%0,%1,%2,%3}, {%4,%5,%6,%7}, {%8,%9}, {%0,%1,%2,%3};"
        : "+f"(d[0]), "+f"(d[1]), "+f"(d[2]), "+f"(d[3])
        : "r"(a[0]), "r"(a[1]), "r"(a[2]), "r"(a[3]), "r"(b[0]), "r"(b[1]));
}

// =============================================================================
// K1: pure streaming convert x -> bf16 hi/lo. Linear float4 reads, uint4 writes.
// grid 16384 blocks x 256 thr; 8 elems/thread.
// =============================================================================
__global__ void __launch_bounds__(256) convert_kernel(const float* __restrict__ x){
    size_t i0 = ((size_t)blockIdx.x*256 + threadIdx.x)*8;
    float4 a = *(const float4*)&x[i0];
    float4 b = *(const float4*)&x[i0+4];
    float v[8] = {a.x,a.y,a.z,a.w,b.x,b.y,b.z,b.w};
    unsigned hw[4], lw[4];
    #pragma unroll
    for(int i=0;i<4;i++){
        __nv_bfloat16 h0 = __float2bfloat16(v[2*i]);
        __nv_bfloat16 h1 = __float2bfloat16(v[2*i+1]);
        __nv_bfloat16 l0 = __float2bfloat16(v[2*i]   - __bfloat162float(h0));
        __nv_bfloat16 l1 = __float2bfloat16(v[2*i+1] - __bfloat162float(h1));
        hw[i] = (unsigned)__bfloat16_as_ushort(h0) | ((unsigned)__bfloat16_as_ushort(h1)<<16);
        lw[i] = (unsigned)__bfloat16_as_ushort(l0) | ((unsigned)__bfloat16_as_ushort(l1)<<16);
    }
    *(uint4*)&g_xh[i0] = make_uint4(hw[0],hw[1],hw[2],hw[3]);
    *(uint4*)&g_xl[i0] = make_uint4(lw[0],lw[1],lw[2],lw[3]);
}

// =============================================================================
// K2: G = X X^T partials via mma.sync bf16x3 (R15 structure, KSPLIT=2)
// =============================================================================
__constant__ int t2_i[3]={0,0,1};
__constant__ int t2_j[3]={0,1,1};

#define CV_TB   18432
#define CV_BUF  73728
#define CV_SMEM (2*CV_BUF)

__device__ __forceinline__ void cov_issue(unsigned sb, int buf, int kg, int i0, int j0,
                                          bool diag, int tid,
                                          const __nv_bfloat16* xh, const __nv_bfloat16* xl){
    #pragma unroll
    for(int p=0;p<8;p++){
        int lin = p*256 + tid;
        int arr = lin>>10, r = (lin>>3)&127, u = lin&7;
        const __nv_bfloat16* s = (arr ? xl : xh) + (size_t)(i0+r)*Tt + kg + u*8;
        cpasync16(sb + buf*CV_BUF + arr*CV_TB + r*144 + u*16, s);
    }
    if(!diag){
        #pragma unroll
        for(int p=0;p<8;p++){
            int lin = p*256 + tid;
            int arr = lin>>10, r = (lin>>3)&127, u = lin&7;
            const __nv_bfloat16* s = (arr ? xl : xh) + (size_t)(j0+r)*Tt + kg + u*8;
            cpasync16(sb + buf*CV_BUF + 2*CV_TB + arr*CV_TB + r*144 + u*16, s);
        }
    }
    asm volatile("cp.async.commit_group;" ::: "memory");
}

__global__ void __launch_bounds__(256) cov_mma(){
    extern __shared__ char sm[];
    unsigned sb = smem_u32(sm);
    int tid = threadIdx.x, w = tid>>5, lane = tid&31;
    int tile = blockIdx.x, b = blockIdx.y, sl = blockIdx.z;
    int i0 = t2_i[tile]*128, j0 = t2_j[tile]*128;
    bool diag = (i0==j0);
    int wc = w&3, wt = w>>2;
    const __nv_bfloat16* xh = g_xh + (size_t)b*Cc*Tt;
    const __nv_bfloat16* xl = g_xl + (size_t)b*Cc*Tt;
    int kbase = sl*(Tt/KSPLIT);
    const int NCH = (Tt/KSPLIT)/64;

    float acc[2][8][4];
    #pragma unroll
    for(int i=0;i<2;i++)
        #pragma unroll
        for(int j=0;j<8;j++)
            #pragma unroll
            for(int r=0;r<4;r++) acc[i][j][r]=0.f;

    cov_issue(sb, 0, kbase,    i0, j0, diag, tid, xh, xl);
    cov_issue(sb, 1, kbase+64, i0, j0, diag, tid, xh, xl);

    #pragma unroll 1
    for(int ch=0; ch<NCH; ++ch){
        int buf = ch&1;
        if(ch==NCH-1) asm volatile("cp.async.wait_group 0;" ::: "memory");
        else          asm volatile("cp.async.wait_group 1;" ::: "memory");
        __syncthreads();
        unsigned abase = sb + buf*CV_BUF;
        unsigned bbase = abase + (diag ? 0u : 2u*CV_TB);
        #pragma unroll
        for(int ks=0; ks<4; ks++){
            unsigned afh[2][4], afl[2][4];
            #pragma unroll
            for(int mt=0; mt<2; mt++){
                unsigned ra = abase + (unsigned)(wc*32 + mt*16 + (lane&15))*144
                            + ((lane>>4)<<4) + ks*32;
                ldsm_x4(afh[mt], ra);
                ldsm_x4(afl[mt], ra + CV_TB);
            }
            #pragma unroll
            for(int ng=0; ng<4; ng++){
                unsigned bfh[4], bfl[4];
                unsigned rb = bbase + (unsigned)(wt*64 + ng*16 + ((lane>>4)<<3) + (lane&7))*144
                            + (((lane>>3)&1)<<4) + ks*32;
                ldsm_x4(bfh, rb);
                ldsm_x4(bfl, rb + CV_TB);
                #pragma unroll
                for(int mt=0; mt<2; mt++){
                    mma_bf16(acc[mt][ng*2  ], afh[mt], &bfh[0]);
                    mma_bf16(acc[mt][ng*2  ], afh[mt], &bfl[0]);
                    mma_bf16(acc[mt][ng*2  ], afl[mt], &bfh[0]);
                    mma_bf16(acc[mt][ng*2+1], afh[mt], &bfh[2]);
                    mma_bf16(acc[mt][ng*2+1], afh[mt], &bfl[2]);
                    mma_bf16(acc[mt][ng*2+1], afl[mt], &bfh[2]);
                }
            }
        }
        __syncthreads();
        if(ch+2<NCH) cov_issue(sb, buf, kbase + (ch+2)*64, i0, j0, diag, tid, xh, xl);
    }

    float* cp = g_covp + ((size_t)sl*Bb + b)*Cc*Cc;
    #pragma unroll
    for(int mt=0; mt<2; mt++){
        int r0 = i0 + wc*32 + mt*16 + (lane>>2);
        #pragma unroll
        for(int nt=0; nt<8; nt++){
            int co = j0 + wt*64 + nt*8 + (lane&3)*2;
            *(float2*)&cp[(size_t)r0*Cc + co]     = make_float2(acc[mt][nt][0], acc[mt][nt][1]);
            *(float2*)&cp[(size_t)(r0+8)*Cc + co] = make_float2(acc[mt][nt][2], acc[mt][nt][3]);
            if(!diag){
                cp[(size_t)co*Cc + r0]       = acc[mt][nt][0];
                cp[(size_t)(co+1)*Cc + r0]   = acc[mt][nt][1];
                cp[(size_t)co*Cc + r0+8]     = acc[mt][nt][2];
                cp[(size_t)(co+1)*Cc + r0+8] = acc[mt][nt][3];
            }
        }
    }
}

// =============================================================================
// K2b: row sums + diagonal of G (2 slices). grid (Bb, 8).
// =============================================================================
__global__ void __launch_bounds__(256) rowsum_kernel(){
    int b = blockIdx.x, rg = blockIdx.y;
    int tid = threadIdx.x, w = tid>>5, lane = tid&31;
    #pragma unroll
    for(int pass=0; pass<4; pass++){
        int r = rg*32 + pass*8 + w;
        float s = 0.f;
        #pragma unroll
        for(int sl=0; sl<KSPLIT; sl++){
            const float* rp = g_covp + ((size_t)sl*Bb + b)*Cc*Cc + (size_t)r*Cc;
            #pragma unroll
            for(int j=0;j<8;j++) s += rp[j*32 + lane];
        }
        #pragma unroll
        for(int d=16; d>0; d>>=1) s += __shfl_xor_sync(0xffffffffu, s, d);
        if(lane==0){
            g_rs[b*Cc+r]=s;
            float dv = 0.f;
            #pragma unroll
            for(int sl=0; sl<KSPLIT; sl++)
                dv += g_covp[((size_t)sl*Bb + b)*Cc*Cc + (size_t)r*Cc + r];
            g_diag[b*Cc+r]=dv;
        }
    }
}

// =============================================================================
// K3: pcc rows + q/k projections. denom derived from trace(G) and S:
// sum_t var = (trace - S/C)/(C-1).  (R13 structure otherwise.)
// =============================================================================
#define PQ_WS   (256*65)
#define PQ_PR   (32*260)
#define PQ_SMEM ((PQ_WS + PQ_PR + 512)*4)

__global__ void __launch_bounds__(256) pccqk_kernel(const float* __restrict__ qw, const float* __restrict__ qb,
                                                    const float* __restrict__ kw, const float* __restrict__ kb){
    extern __shared__ float sdyn[];
    float* ws   = sdyn;
    float* prow = ws + PQ_WS;
    float* srs  = prow + PQ_PR;      // 256: rs/C
    float* sdg  = srs + 256;         // 256: diag
    __shared__ float sden, sSc;
    int tid = threadIdx.x;
    int cg = blockIdx.x, b = blockIdx.y;
    int c0 = cg*32;

    srs[tid] = g_rs[b*Cc + tid] * (1.0f/Cc);
    sdg[tid] = g_diag[b*Cc + tid];
    #pragma unroll
    for(int p=0;p<64;p++){
        int idx = p*256 + tid;
        int e = idx>>8, d = idx&255;
        float v = (e<32) ? qw[e*Cc+d] : kw[(e-32)*Cc+d];
        ws[d*65 + ((e&7)<<3) + (e>>3)] = v;
    }
    if(tid==0){
        float S=0.f, tr=0.f;
        #pragma unroll 8
        for(int i=0;i<Cc;i++){ S += srs[i]; tr += sdg[i]; }   // S = S_tot/C
        sSc = S*(1.0f/Cc);                                     // S_tot/C²
        sden = (float)(Cc-1)/(tr - S);                         // 1/Σvar
    }
    __syncthreads();

    float Sc = sSc, den = sden;
    #pragma unroll
    for(int p=0;p<8;p++){
        int idx = p*256 + tid;
        int r = idx>>6, d4 = (idx&63)*4;
        size_t off = ((size_t)(c0+r))*Cc + (size_t)b*Cc*Cc + d4;
        float4 v0 = *(const float4*)&g_covp[off];
        float4 v1 = *(const float4*)&g_covp[(size_t)SL + off];
        float rc = srs[c0+r] - Sc;
        prow[r*260 + d4+0] = (v0.x+v1.x - rc - srs[d4+0])*den;
        prow[r*260 + d4+1] = (v0.y+v1.y - rc - srs[d4+1])*den;
        prow[r*260 + d4+2] = (v0.z+v1.z - rc - srs[d4+2])*den;
        prow[r*260 + d4+3] = (v0.w+v1.w - rc - srs[d4+3])*den;
    }
    __syncthreads();

    int r = tid>>3, g = tid&7;
    float acc[8];
    #pragma unroll
    for(int j=0;j<8;j++){
        int e = g*8 + j;
        acc[j] = (e<32) ? qb[e] : kb[e-32];
    }
    const float* pr = &prow[r*260];
    #pragma unroll 4
    for(int d=0; d<Cc; d++){
        float pv = pr[d];
        const float* wd = &ws[d*65 + g];
        #pragma unroll
        for(int j=0;j<8;j++) acc[j] += pv * wd[j*8];
    }
    int c = c0 + r;
    if(g<4){
        float* qp = &g_q[((size_t)b*Cc + c)*32 + g*8];
        *(float4*)&qp[0] = make_float4(acc[0],acc[1],acc[2],acc[3]);
        *(float4*)&qp[4] = make_float4(acc[4],acc[5],acc[6],acc[7]);
    }else{
        float* kp = &g_k[((size_t)b*Cc + c)*32 + (g-4)*8];
        *(float4*)&kp[0] = make_float4(acc[0],acc[1],acc[2],acc[3]);
        *(float4*)&kp[4] = make_float4(acc[4],acc[5],acc[6],acc[7]);
    }
}

// =============================================================================
// K4: scores + softmax, warp-per-query (EXACT R15 — known-good)
// =============================================================================
__global__ void __launch_bounds__(256) attn_kernel(float* __restrict__ out){
    int bg = blockIdx.x, b = blockIdx.y;
    int tid = threadIdx.x, w = tid>>5, lane = tid&31;
    __shared__ float ks[256][36];
    __shared__ float qs[32][36];
    const float* kp = g_k + (size_t)b*Cc*32;
    int c0 = bg*32;
    #pragma unroll
    for(int p=0;p<8;p++){
        int idx = tid + p*256;
        int d = idx>>3, e4 = (idx&7)*4;
        *(float4*)&ks[d][e4] = *(const float4*)&kp[d*32 + e4];
    }
    {
        int q = tid>>3, e4 = (tid&7)*4;
        *(float4*)&qs[q][e4] = *(const float4*)&g_q[((size_t)b*Cc + c0 + q)*32 + e4];
    }
    __syncthreads();
    float* ao = out + OUT_ELEMS + ((size_t)b*Cc + c0)*Cc;
    #pragma unroll
    for(int qi=0; qi<4; qi++){
        int q = w*4 + qi;
        float s[8];
        #pragma unroll
        for(int m=0;m<8;m++) s[m]=0.f;
        #pragma unroll
        for(int e4=0;e4<8;e4++){
            float4 qv = *(const float4*)&qs[q][e4*4];
            #pragma unroll
            for(int m=0;m<8;m++){
                float4 kv = *(const float4*)&ks[m*32+lane][e4*4];
                s[m] += qv.x*kv.x + qv.y*kv.y + qv.z*kv.z + qv.w*kv.w;
            }
        }
        float mx = s[0]*(1.0f/16.0f);
        #pragma unroll
        for(int m=0;m<8;m++){ s[m] *= (1.0f/16.0f); mx = fmaxf(mx, s[m]); }
        #pragma unroll
        for(int d=16; d>0; d>>=1) mx = fmaxf(mx, __shfl_xor_sync(0xffffffffu, mx, d));
        float ev[8], sm=0.f;
        #pragma unroll
        for(int m=0;m<8;m++){ ev[m] = expf(s[m]-mx); sm += ev[m]; }
        #pragma unroll
        for(int d=16; d>0; d>>=1) sm += __shfl_xor_sync(0xffffffffu, sm, d);
        float inv = 1.0f/sm;
        #pragma unroll
        for(int m=0;m<8;m++){
            float a = ev[m]*inv;
            size_t idx = ((size_t)b*Cc + c0 + q)*Cc + m*32 + lane;
            ao[(size_t)q*Cc + m*32 + lane] = a;
            __nv_bfloat16 h = __float2bfloat16(a);
            g_attn_h[idx] = h;
            g_attn_l[idx] = __float2bfloat16(a - __bfloat162float(h));
        }
    }
}

// =============================================================================
// K5: out = attn @ x, c-supertile (EXACT R15 — known-good)
// =============================================================================
#define O2_AL   36864
#define O2_B    73728
#define O2_BL   17408
#define O2_BUF  108544
#define O2_SMEM (2*O2_BUF)

__device__ __forceinline__ void og2_issue(unsigned sb, int buf, int d0, int t0,
                                          int tid,
                                          const __nv_bfloat16* ah, const __nv_bfloat16* al,
                                          const __nv_bfloat16* xh, const __nv_bfloat16* xl){
    unsigned dst = sb + buf*O2_BUF;
    #pragma unroll
    for(int p=0;p<16;p++){
        int lin = p*256 + tid;
        int arr = lin>>11, r = (lin>>3)&255, u = lin&7;
        const __nv_bfloat16* s = (arr ? al : ah) + (size_t)r*Cc + d0 + u*8;
        cpasync16(dst + arr*O2_AL + r*144 + u*16, s);
    }
    #pragma unroll
    for(int p=0;p<8;p++){
        int lin = p*256 + tid;
        int arr = lin>>10, la = lin&1023;
        int r = la>>4, u = la&15;
        const __nv_bfloat16* s = (arr ? xl : xh) + (size_t)(d0+r)*Tt + t0 + u*8;
        cpasync16(dst + O2_B + arr*O2_BL + r*272 + u*16, s);
    }
    asm volatile("cp.async.commit_group;" ::: "memory");
}

__global__ void __launch_bounds__(256) out_gemm_mma(float* __restrict__ out){
    extern __shared__ char sm[];
    unsigned sb = smem_u32(sm);
    int tid = threadIdx.x, w = tid>>5, lane = tid&31;
    int t0 = blockIdx.x*128, b = blockIdx.y;
    const __nv_bfloat16* xh = g_xh + (size_t)b*Cc*Tt;
    const __nv_bfloat16* xl = g_xl + (size_t)b*Cc*Tt;
    const __nv_bfloat16* ah = g_attn_h + (size_t)b*Cc*Cc;
    const __nv_bfloat16* al = g_attn_l + (size_t)b*Cc*Cc;
    int wc = w&3, wt = w>>2;

    float acc[4][8][4];
    #pragma unroll
    for(int i=0;i<4;i++)
        #pragma unroll
        for(int j=0;j<8;j++)
            #pragma unroll
            for(int r=0;r<4;r++) acc[i][j][r]=0.f;

    og2_issue(sb, 0, 0,  t0, tid, ah, al, xh, xl);
    og2_issue(sb, 1, 64, t0, tid, ah, al, xh, xl);

    #pragma unroll 1
    for(int ch=0; ch<4; ++ch){
        int buf = ch&1;
        if(ch==3) asm volatile("cp.async.wait_group 0;" ::: "memory");
        else      asm volatile("cp.async.wait_group 1;" ::: "memory");
        __syncthreads();
        unsigned abase = sb + buf*O2_BUF;
        unsigned bbase = abase + O2_B;
        #pragma unroll
        for(int ks=0; ks<4; ks++){
            int k0 = ks*16;
            unsigned bfh[4][4], bfl[4][4];
            int kk = k0 + (lane&7) + (((lane>>3)&1)<<3);
            #pragma unroll
            for(int ng=0; ng<4; ng++){
                int tt = wt*64 + ng*16 + (((lane>>4)&1)<<3);
                unsigned rb = bbase + (unsigned)kk*272 + tt*2;
                ldsm_x4_t(bfh[ng], rb);
                ldsm_x4_t(bfl[ng], rb + O2_BL);
            }
            #pragma unroll
            for(int mt=0; mt<4; mt++){
                unsigned afh[4], afl[4];
                unsigned ra = abase + (unsigned)(wc*64 + mt*16 + (lane&15))*144
                            + k0*2 + ((lane>>4)<<4);
                ldsm_x4(afh, ra);
                ldsm_x4(afl, ra + O2_AL);
                #pragma unroll
                for(int ng=0; ng<4; ng++){
                    mma_bf16(acc[mt][ng*2  ], afh, &bfh[ng][0]);
                    mma_bf16(acc[mt][ng*2  ], afh, &bfl[ng][0]);
                    mma_bf16(acc[mt][ng*2  ], afl, &bfh[ng][0]);
                    mma_bf16(acc[mt][ng*2+1], afh, &bfh[ng][2]);
                    mma_bf16(acc[mt][ng*2+1], afh, &bfl[ng][2]);
                    mma_bf16(acc[mt][ng*2+1], afl, &bfh[ng][2]);
                }
            }
        }
        __syncthreads();
        if(ch+2<4) og2_issue(sb, buf, (ch+2)*64, t0, tid, ah, al, xh, xl);
    }

    float* ob = out + (size_t)b*Cc*Tt;
    #pragma unroll
    for(int mt=0; mt<4; mt++){
        int r0 = wc*64 + mt*16 + (lane>>2);
        #pragma unroll
        for(int nt=0; nt<8; nt++){
            int t = t0 + wt*64 + nt*8 + (lane&3)*2;
            *(float2*)&ob[(size_t)r0*Tt + t]     = make_float2(acc[mt][nt][0], acc[mt][nt][1]);
            *(float2*)&ob[(size_t)(r0+8)*Tt + t] = make_float2(acc[mt][nt][2], acc[mt][nt][3]);
        }
    }
}

// =============================================================================
extern "C" void kernel_launch(void* const* d_in, const int* in_sizes, int n_in,
                              void* d_out, int out_size){
    const float* x  = (const float*)d_in[0];
    const float* qw = (const float*)d_in[1];
    const float* qb = (const float*)d_in[2];
    const float* kw = (const float*)d_in[3];
    const float* kb = (const float*)d_in[4];
    float* out = (float*)d_out;

    cudaFuncSetAttribute(out_gemm_mma, cudaFuncAttributeMaxDynamicSharedMemorySize, O2_SMEM);
    cudaFuncSetAttribute(cov_mma, cudaFuncAttributeMaxDynamicSharedMemorySize, CV_SMEM);
    cudaFuncSetAttribute(pccqk_kernel, cudaFuncAttributeMaxDynamicSharedMemorySize, PQ_SMEM);

    convert_kernel<<<(Bb*Cc*Tt)/(256*8), 256>>>(x);
    cov_mma      <<<dim3(3, Bb, KSPLIT), 256, CV_SMEM>>>();
    rowsum_kernel<<<dim3(Bb, 8), 256>>>();
    pccqk_kernel <<<dim3(8, Bb), 256, PQ_SMEM>>>(qw, qb, kw, kb);
    attn_kernel  <<<dim3(Cc/32, Bb), 256>>>(out);
    out_gemm_mma <<<dim3(Tt/128, Bb), 256, O2_SMEM>>>(out);
}